// round 5
// baseline (speedup 1.0000x reference)
#include <cuda_runtime.h>

#define NB   2
#define LSEQ 2048
#define EMB  1024
#define NHD  16
#define HD   64

__device__ float g_q[NB * LSEQ * EMB];
__device__ float g_k[NB * LSEQ * EMB];
__device__ float g_v[NB * LSEQ * EMB];
__device__ float g_ctx[NB * LSEQ * EMB];

__device__ __forceinline__ unsigned f2tf(float x) {
    unsigned u;
    asm("cvt.rna.tf32.f32 %0, %1;" : "=r"(u) : "f"(x));
    return u;
}

__device__ __forceinline__ void mma_tf32(float* d,
                                         unsigned a0, unsigned a1, unsigned a2, unsigned a3,
                                         unsigned b0, unsigned b1) {
    asm("mma.sync.aligned.m16n8k8.row.col.f32.tf32.tf32.f32 "
        "{%0,%1,%2,%3}, {%4,%5,%6,%7}, {%8,%9}, {%0,%1,%2,%3};\n"
        : "+f"(d[0]), "+f"(d[1]), "+f"(d[2]), "+f"(d[3])
        : "r"(a0), "r"(a1), "r"(a2), "r"(a3), "r"(b0), "r"(b1));
}

// ---------------- Kernel 1: per-head projections (exact fp32) ----------------
// x viewed as (N*L*H, 64) row-major. out[r][e] = sum_d x[r][d]*W[e][d] (+bq for q)
__global__ __launch_bounds__(256) void proj_kernel(
    const float* __restrict__ xq, const float* __restrict__ xk, const float* __restrict__ xv,
    const float* __restrict__ Wq, const float* __restrict__ Wk, const float* __restrict__ Wv,
    const float* __restrict__ bq)
{
    __shared__ float Wt[64][68];  // Wt[d][e] = W[e][d]
    __shared__ float Xt[64][68];  // Xt[d][r]

    const int which = blockIdx.y;
    const float* x   = (which == 0) ? xq : (which == 1) ? xk : xv;
    const float* W   = (which == 0) ? Wq : (which == 1) ? Wk : Wv;
    float*       out = (which == 0) ? g_q : (which == 1) ? g_k : g_v;

    const int t  = threadIdx.x;
    const int rb = blockIdx.x * 64;

#pragma unroll
    for (int i = 0; i < 4; i++) {
        int f4 = t + i * 256;
        int r  = f4 >> 4;
        int d0 = (f4 & 15) << 2;
        float4 w = *(const float4*)(W + r * 64 + d0);
        Wt[d0 + 0][r] = w.x; Wt[d0 + 1][r] = w.y; Wt[d0 + 2][r] = w.z; Wt[d0 + 3][r] = w.w;
        float4 xr = *(const float4*)(x + (size_t)rb * 64 + (size_t)f4 * 4);
        Xt[d0 + 0][r] = xr.x; Xt[d0 + 1][r] = xr.y; Xt[d0 + 2][r] = xr.z; Xt[d0 + 3][r] = xr.w;
    }
    __syncthreads();

    const int r0 = (t >> 4) << 2;
    const int e0 = (t & 15) << 2;
    float acc[4][4];
#pragma unroll
    for (int j = 0; j < 4; j++)
#pragma unroll
        for (int i = 0; i < 4; i++) acc[j][i] = 0.f;

#pragma unroll
    for (int d = 0; d < 64; d++) {
        float4 w4 = *(const float4*)&Wt[d][e0];
        float4 x4 = *(const float4*)&Xt[d][r0];
        float xs[4] = {x4.x, x4.y, x4.z, x4.w};
        float ws[4] = {w4.x, w4.y, w4.z, w4.w};
#pragma unroll
        for (int j = 0; j < 4; j++)
#pragma unroll
            for (int i = 0; i < 4; i++) acc[j][i] += xs[j] * ws[i];
    }

    float bv[4] = {0.f, 0.f, 0.f, 0.f};
    if (which == 0) { bv[0] = bq[e0]; bv[1] = bq[e0+1]; bv[2] = bq[e0+2]; bv[3] = bq[e0+3]; }
#pragma unroll
    for (int j = 0; j < 4; j++) {
        float4 o;
        o.x = acc[j][0] + bv[0]; o.y = acc[j][1] + bv[1];
        o.z = acc[j][2] + bv[2]; o.w = acc[j][3] + bv[3];
        *(float4*)(out + (size_t)(rb + r0 + j) * 64 + e0) = o;
    }
}

// ---------------- Kernel 2: flash attention (tf32 mma) ----------------
// grid (L/64, N*H), 128 threads = 4 warps x 16 q-rows.
__global__ __launch_bounds__(128) void flash_kernel(const int* __restrict__ mask)
{
    __shared__ float Ks[64][68];
    __shared__ float Vs[64][72];
    __shared__ int   Ms[64];

    const int t    = threadIdx.x;
    const int warp = t >> 5;
    const int lane = t & 31;
    const int qn   = lane >> 2;
    const int q4   = lane & 3;

    const int nh = blockIdx.y;
    const int n  = nh >> 4;
    const int h  = nh & 15;
    const int qbase = blockIdx.x * 64;

    const float* Qp = g_q + (size_t)n * LSEQ * EMB + h * HD;
    const float* Kp = g_k + (size_t)n * LSEQ * EMB + h * HD;
    const float* Vp = g_v + (size_t)n * LSEQ * EMB + h * HD;

    // stage Q tile (tf32 bits) through Ks, pull A-fragments
#pragma unroll
    for (int i = 0; i < 8; i++) {
        int f4  = t + i * 128;
        int row = f4 >> 4;
        int d0  = (f4 & 15) << 2;
        float4 v = *(const float4*)(Qp + (size_t)(qbase + row) * EMB + d0);
        Ks[row][d0 + 0] = __uint_as_float(f2tf(v.x));
        Ks[row][d0 + 1] = __uint_as_float(f2tf(v.y));
        Ks[row][d0 + 2] = __uint_as_float(f2tf(v.z));
        Ks[row][d0 + 3] = __uint_as_float(f2tf(v.w));
    }
    __syncthreads();

    unsigned qa[8][4];
    const int qr = warp * 16 + qn;
#pragma unroll
    for (int ks = 0; ks < 8; ks++) {
        qa[ks][0] = __float_as_uint(Ks[qr][ks * 8 + q4]);
        qa[ks][1] = __float_as_uint(Ks[qr + 8][ks * 8 + q4]);
        qa[ks][2] = __float_as_uint(Ks[qr][ks * 8 + q4 + 4]);
        qa[ks][3] = __float_as_uint(Ks[qr + 8][ks * 8 + q4 + 4]);
    }

    float o[8][4];
#pragma unroll
    for (int i = 0; i < 8; i++) { o[i][0] = o[i][1] = o[i][2] = o[i][3] = 0.f; }
    float mrow0 = -3.0e38f, mrow1 = -3.0e38f;
    float lrow0 = 0.f, lrow1 = 0.f;

    for (int kt = 0; kt < LSEQ / 64; kt++) {
        const int kb = kt * 64;
        __syncthreads();

#pragma unroll
        for (int i = 0; i < 8; i++) {
            int f4  = t + i * 128;
            int row = f4 >> 4;
            int d0  = (f4 & 15) << 2;
            float4 kv = *(const float4*)(Kp + (size_t)(kb + row) * EMB + d0);
            Ks[row][d0 + 0] = __uint_as_float(f2tf(kv.x));
            Ks[row][d0 + 1] = __uint_as_float(f2tf(kv.y));
            Ks[row][d0 + 2] = __uint_as_float(f2tf(kv.z));
            Ks[row][d0 + 3] = __uint_as_float(f2tf(kv.w));
            float4 vv = *(const float4*)(Vp + (size_t)(kb + row) * EMB + d0);
            Vs[row][d0 + 0] = __uint_as_float(f2tf(vv.x));
            Vs[row][d0 + 1] = __uint_as_float(f2tf(vv.y));
            Vs[row][d0 + 2] = __uint_as_float(f2tf(vv.z));
            Vs[row][d0 + 3] = __uint_as_float(f2tf(vv.w));
        }
        if (t < 64) Ms[t] = mask[n * LSEQ + kb + t];
        __syncthreads();

        // S = Q @ K^T
        float s[8][4];
#pragma unroll
        for (int i = 0; i < 8; i++) { s[i][0] = s[i][1] = s[i][2] = s[i][3] = 0.f; }
#pragma unroll
        for (int ks = 0; ks < 8; ks++) {
#pragma unroll
            for (int nt = 0; nt < 8; nt++) {
                unsigned b0 = __float_as_uint(Ks[nt * 8 + qn][ks * 8 + q4]);
                unsigned b1 = __float_as_uint(Ks[nt * 8 + qn][ks * 8 + q4 + 4]);
                mma_tf32(s[nt], qa[ks][0], qa[ks][1], qa[ks][2], qa[ks][3], b0, b1);
            }
        }

        // mask then scale by 1/sqrt(E)=1/32 (ref masks before scaling)
        const float scl = 0.03125f;
#pragma unroll
        for (int nt = 0; nt < 8; nt++) {
            int m0 = Ms[nt * 8 + 2 * q4];
            int m1 = Ms[nt * 8 + 2 * q4 + 1];
            s[nt][0] = m0 ? s[nt][0] * scl : -3.125e18f;
            s[nt][1] = m1 ? s[nt][1] * scl : -3.125e18f;
            s[nt][2] = m0 ? s[nt][2] * scl : -3.125e18f;
            s[nt][3] = m1 ? s[nt][3] * scl : -3.125e18f;
        }

        // online softmax (rows qn and qn+8)
        float mx0 = s[0][0], mx1 = s[0][2];
#pragma unroll
        for (int nt = 0; nt < 8; nt++) {
            mx0 = fmaxf(mx0, fmaxf(s[nt][0], s[nt][1]));
            mx1 = fmaxf(mx1, fmaxf(s[nt][2], s[nt][3]));
        }
        mx0 = fmaxf(mx0, __shfl_xor_sync(0xffffffffu, mx0, 1));
        mx0 = fmaxf(mx0, __shfl_xor_sync(0xffffffffu, mx0, 2));
        mx1 = fmaxf(mx1, __shfl_xor_sync(0xffffffffu, mx1, 1));
        mx1 = fmaxf(mx1, __shfl_xor_sync(0xffffffffu, mx1, 2));

        float mn0 = fmaxf(mrow0, mx0);
        float mn1 = fmaxf(mrow1, mx1);
        float c0 = __expf(mrow0 - mn0);
        float c1 = __expf(mrow1 - mn1);
        mrow0 = mn0; mrow1 = mn1;

        float sum0 = 0.f, sum1 = 0.f;
#pragma unroll
        for (int nt = 0; nt < 8; nt++) {
            s[nt][0] = __expf(s[nt][0] - mn0); sum0 += s[nt][0];
            s[nt][1] = __expf(s[nt][1] - mn0); sum0 += s[nt][1];
            s[nt][2] = __expf(s[nt][2] - mn1); sum1 += s[nt][2];
            s[nt][3] = __expf(s[nt][3] - mn1); sum1 += s[nt][3];
        }
        sum0 += __shfl_xor_sync(0xffffffffu, sum0, 1);
        sum0 += __shfl_xor_sync(0xffffffffu, sum0, 2);
        sum1 += __shfl_xor_sync(0xffffffffu, sum1, 1);
        sum1 += __shfl_xor_sync(0xffffffffu, sum1, 2);
        lrow0 = lrow0 * c0 + sum0;
        lrow1 = lrow1 * c1 + sum1;

#pragma unroll
        for (int nt = 0; nt < 8; nt++) {
            o[nt][0] *= c0; o[nt][1] *= c0; o[nt][2] *= c1; o[nt][3] *= c1;
            s[nt][0] = __uint_as_float(f2tf(s[nt][0]));
            s[nt][1] = __uint_as_float(f2tf(s[nt][1]));
            s[nt][2] = __uint_as_float(f2tf(s[nt][2]));
            s[nt][3] = __uint_as_float(f2tf(s[nt][3]));
        }

        // O += P @ V. C-frag -> A-frag via quad shuffles.
        const int  sl1 = (lane & 28) | (q4 >> 1);
        const int  sl2 = sl1 + 2;
        const bool hi  = (q4 & 1);
#pragma unroll
        for (int ks = 0; ks < 8; ks++) {
            float u0 = __shfl_sync(0xffffffffu, s[ks][0], sl1);
            float u1 = __shfl_sync(0xffffffffu, s[ks][1], sl1);
            float u2 = __shfl_sync(0xffffffffu, s[ks][2], sl1);
            float u3 = __shfl_sync(0xffffffffu, s[ks][3], sl1);
            float w0 = __shfl_sync(0xffffffffu, s[ks][0], sl2);
            float w1 = __shfl_sync(0xffffffffu, s[ks][1], sl2);
            float w2 = __shfl_sync(0xffffffffu, s[ks][2], sl2);
            float w3 = __shfl_sync(0xffffffffu, s[ks][3], sl2);
            unsigned a0 = __float_as_uint(hi ? u1 : u0);
            unsigned a1 = __float_as_uint(hi ? u3 : u2);
            unsigned a2 = __float_as_uint(hi ? w1 : w0);
            unsigned a3 = __float_as_uint(hi ? w3 : w2);
#pragma unroll
            for (int nt = 0; nt < 8; nt++) {
                unsigned b0 = __float_as_uint(Vs[ks * 8 + q4][nt * 8 + qn]);
                unsigned b1 = __float_as_uint(Vs[ks * 8 + q4 + 4][nt * 8 + qn]);
                mma_tf32(o[nt], a0, a1, a2, a3, b0, b1);
            }
        }
    }

    const float inv0 = 1.f / lrow0;
    const float inv1 = 1.f / lrow1;
    float* Op = g_ctx + (size_t)(n * LSEQ + qbase) * EMB + h * HD;
    const int row = warp * 16 + qn;
#pragma unroll
    for (int nt = 0; nt < 8; nt++) {
        int col = nt * 8 + 2 * q4;
        float2 v0; v0.x = o[nt][0] * inv0; v0.y = o[nt][1] * inv0;
        *(float2*)(Op + (size_t)row * EMB + col) = v0;
        float2 v1; v1.x = o[nt][2] * inv1; v1.y = o[nt][3] * inv1;
        *(float2*)(Op + (size_t)(row + 8) * EMB + col) = v1;
    }
}

// ---------------- Kernel 3: out = ctx @ Wo^T + bo (tf32 mma) ----------------
// M=4096, N=1024, K=1024. 64x64 tile, 4 warps, K-step 32. grid (16, 64).
__global__ __launch_bounds__(128) void ogemm_kernel(
    const float* __restrict__ Wo, const float* __restrict__ bo, float* __restrict__ out)
{
    __shared__ float As[64][36];
    __shared__ float Bs[32][72];

    const int t    = threadIdx.x;
    const int warp = t >> 5;
    const int lane = t & 31;
    const int qn   = lane >> 2;
    const int q4   = lane & 3;
    const int mb   = blockIdx.y * 64;
    const int nb   = blockIdx.x * 64;

    float acc[8][4];
#pragma unroll
    for (int i = 0; i < 8; i++) { acc[i][0] = acc[i][1] = acc[i][2] = acc[i][3] = 0.f; }

    for (int kb = 0; kb < 1024; kb += 32) {
        __syncthreads();
#pragma unroll
        for (int i = 0; i < 4; i++) {
            int f4  = t + i * 128;
            int row = f4 >> 3;
            int k0  = (f4 & 7) << 2;
            float4 a = *(const float4*)(g_ctx + (size_t)(mb + row) * 1024 + kb + k0);
            As[row][k0 + 0] = __uint_as_float(f2tf(a.x));
            As[row][k0 + 1] = __uint_as_float(f2tf(a.y));
            As[row][k0 + 2] = __uint_as_float(f2tf(a.z));
            As[row][k0 + 3] = __uint_as_float(f2tf(a.w));
            float4 b = *(const float4*)(Wo + (size_t)(nb + row) * 1024 + kb + k0);
            Bs[k0 + 0][row] = __uint_as_float(f2tf(b.x));
            Bs[k0 + 1][row] = __uint_as_float(f2tf(b.y));
            Bs[k0 + 2][row] = __uint_as_float(f2tf(b.z));
            Bs[k0 + 3][row] = __uint_as_float(f2tf(b.w));
        }
        __syncthreads();

        const int r = warp * 16 + qn;
#pragma unroll
        for (int ks = 0; ks < 4; ks++) {
            unsigned a0 = __float_as_uint(As[r][ks * 8 + q4]);
            unsigned a1 = __float_as_uint(As[r + 8][ks * 8 + q4]);
            unsigned a2 = __float_as_uint(As[r][ks * 8 + q4 + 4]);
            unsigned a3 = __float_as_uint(As[r + 8][ks * 8 + q4 + 4]);
#pragma unroll
            for (int nt = 0; nt < 8; nt++) {
                unsigned b0 = __float_as_uint(Bs[ks * 8 + q4][nt * 8 + qn]);
                unsigned b1 = __float_as_uint(Bs[ks * 8 + q4 + 4][nt * 8 + qn]);
                mma_tf32(acc[nt], a0, a1, a2, a3, b0, b1);
            }
        }
    }

    const int row = warp * 16 + qn;
#pragma unroll
    for (int nt = 0; nt < 8; nt++) {
        int col = nt * 8 + 2 * q4;
        float b0 = bo[nb + col], b1 = bo[nb + col + 1];
        float2 v0; v0.x = acc[nt][0] + b0; v0.y = acc[nt][1] + b1;
        *(float2*)(out + (size_t)(mb + row) * 1024 + nb + col) = v0;
        float2 v1; v1.x = acc[nt][2] + b0; v1.y = acc[nt][3] + b1;
        *(float2*)(out + (size_t)(mb + row + 8) * 1024 + nb + col) = v1;
    }
}

extern "C" void kernel_launch(void* const* d_in, const int* in_sizes, int n_in,
                              void* d_out, int out_size) {
    const float* values = (const float*)d_in[0];
    const float* key    = (const float*)d_in[1];
    const float* query  = (const float*)d_in[2];
    const int*   mask   = (const int*)d_in[3];
    const float* Wv     = (const float*)d_in[4];
    const float* Wk     = (const float*)d_in[5];
    const float* Wq     = (const float*)d_in[6];
    const float* bq     = (const float*)d_in[7];
    const float* Wo     = (const float*)d_in[8];
    const float* bo     = (const float*)d_in[9];
    float* out = (float*)d_out;

    proj_kernel<<<dim3(NB * LSEQ * NHD / 64, 3), 256>>>(query, key, values, Wq, Wk, Wv, bq);
    flash_kernel<<<dim3(LSEQ / 64, NB * NHD), 128>>>(mask);
    ogemm_kernel<<<dim3(EMB / 64, NB * LSEQ / 64), 128>>>(Wo, bo, out);
}

// round 6
// speedup vs baseline: 1.2015x; 1.2015x over previous
#include <cuda_runtime.h>

#define NB   2
#define LSEQ 2048
#define EMB  1024
#define NHD  16
#define HD   64

__device__ float g_q[NB * LSEQ * EMB];
__device__ float g_k[NB * LSEQ * EMB];
__device__ float g_v[NB * LSEQ * EMB];
__device__ float g_ctx[NB * LSEQ * EMB];

__device__ __forceinline__ unsigned f2tf(float x) {
    unsigned u;
    asm("cvt.rna.tf32.f32 %0, %1;" : "=r"(u) : "f"(x));
    return u;
}

__device__ __forceinline__ void mma_tf32(float* d,
                                         unsigned a0, unsigned a1, unsigned a2, unsigned a3,
                                         unsigned b0, unsigned b1) {
    asm("mma.sync.aligned.m16n8k8.row.col.f32.tf32.tf32.f32 "
        "{%0,%1,%2,%3}, {%4,%5,%6,%7}, {%8,%9}, {%0,%1,%2,%3};\n"
        : "+f"(d[0]), "+f"(d[1]), "+f"(d[2]), "+f"(d[3])
        : "r"(a0), "r"(a1), "r"(a2), "r"(a3), "r"(b0), "r"(b1));
}

__device__ __forceinline__ void cpa16(void* s, const void* g) {
    unsigned sa = (unsigned)__cvta_generic_to_shared(s);
    asm volatile("cp.async.cg.shared.global [%0], [%1], 16;\n"
                 :: "r"(sa), "l"(__cvta_generic_to_global(g)));
}
__device__ __forceinline__ void cpa_commit() { asm volatile("cp.async.commit_group;\n"); }

// ---------------- Kernel 1: per-head projections via tf32 mma ----------------
// x viewed as (N*L*H, 64). out[r][e] = sum_d x[r][d]*W[e][d] (+bq for q).
// Inputs truncated to tf32; outputs rounded (RNA) to tf32 bits for downstream.
__global__ __launch_bounds__(128) void proj_kernel(
    const float* __restrict__ xq, const float* __restrict__ xk, const float* __restrict__ xv,
    const float* __restrict__ Wq, const float* __restrict__ Wk, const float* __restrict__ Wv,
    const float* __restrict__ bq)
{
    __shared__ float Xs[64][68];
    __shared__ float Ws2[64][68];

    const int which = blockIdx.y;
    const float* x   = (which == 0) ? xq : (which == 1) ? xk : xv;
    const float* W   = (which == 0) ? Wq : (which == 1) ? Wk : Wv;
    float*       out = (which == 0) ? g_q : (which == 1) ? g_k : g_v;

    const int t    = threadIdx.x;
    const int warp = t >> 5;
    const int lane = t & 31;
    const int qn   = lane >> 2;
    const int q4   = lane & 3;
    const int rb   = blockIdx.x * 64;

#pragma unroll
    for (int i = 0; i < 8; i++) {
        int f4  = t + i * 128;
        int row = f4 >> 4;
        int d0  = (f4 & 15) << 2;
        *(float4*)&Xs[row][d0]  = *(const float4*)(x + (size_t)(rb + row) * 64 + d0);
        *(float4*)&Ws2[row][d0] = *(const float4*)(W + row * 64 + d0);
    }
    __syncthreads();

    float acc[8][4];
#pragma unroll
    for (int i = 0; i < 8; i++) { acc[i][0] = acc[i][1] = acc[i][2] = acc[i][3] = 0.f; }

    const int r = warp * 16 + qn;
#pragma unroll
    for (int ks = 0; ks < 8; ks++) {
        unsigned a0 = __float_as_uint(Xs[r][ks * 8 + q4]);
        unsigned a1 = __float_as_uint(Xs[r + 8][ks * 8 + q4]);
        unsigned a2 = __float_as_uint(Xs[r][ks * 8 + q4 + 4]);
        unsigned a3 = __float_as_uint(Xs[r + 8][ks * 8 + q4 + 4]);
#pragma unroll
        for (int nt = 0; nt < 8; nt++) {
            unsigned b0 = __float_as_uint(Ws2[nt * 8 + qn][ks * 8 + q4]);
            unsigned b1 = __float_as_uint(Ws2[nt * 8 + qn][ks * 8 + q4 + 4]);
            mma_tf32(acc[nt], a0, a1, a2, a3, b0, b1);
        }
    }

#pragma unroll
    for (int nt = 0; nt < 8; nt++) {
        int col = nt * 8 + 2 * q4;
        float b0 = 0.f, b1 = 0.f;
        if (which == 0) { b0 = bq[col]; b1 = bq[col + 1]; }
        float2 v0;
        v0.x = __uint_as_float(f2tf(acc[nt][0] + b0));
        v0.y = __uint_as_float(f2tf(acc[nt][1] + b1));
        *(float2*)(out + (size_t)(rb + r) * 64 + col) = v0;
        float2 v1;
        v1.x = __uint_as_float(f2tf(acc[nt][2] + b0));
        v1.y = __uint_as_float(f2tf(acc[nt][3] + b1));
        *(float2*)(out + (size_t)(rb + r + 8) * 64 + col) = v1;
    }
}

// ---------------- Kernel 2: flash attention (tf32 mma, cp.async pipeline) ----
// grid (L/64, N*H), 128 threads = 4 warps x 16 q-rows. Double-buffered K/V/mask.
#define KS_STRIDE 68
#define VS_STRIDE 72
#define KS_TILE (64 * KS_STRIDE)   // 4352 floats
#define VS_TILE (64 * VS_STRIDE)   // 4608 floats
#define FLASH_SMEM_BYTES ((2 * KS_TILE + 2 * VS_TILE) * 4 + 2 * 64 * 4)

__global__ __launch_bounds__(128) void flash_kernel(const int* __restrict__ mask)
{
    extern __shared__ float fsm[];
    float* KS = fsm;                       // [2][64][68]
    float* VS = fsm + 2 * KS_TILE;         // [2][64][72]
    int*   MS = (int*)(fsm + 2 * KS_TILE + 2 * VS_TILE);  // [2][64]

    const int t    = threadIdx.x;
    const int warp = t >> 5;
    const int lane = t & 31;
    const int qn   = lane >> 2;
    const int q4   = lane & 3;

    const int nh = blockIdx.y;
    const int n  = nh >> 4;
    const int h  = nh & 15;
    const int qbase = blockIdx.x * 64;

    const float* Qp = g_q + (size_t)n * LSEQ * EMB + h * HD;
    const float* Kp = g_k + (size_t)n * LSEQ * EMB + h * HD;
    const float* Vp = g_v + (size_t)n * LSEQ * EMB + h * HD;
    const int* maskp = mask + n * LSEQ;

    auto load_tile = [&](int kt, int buf) {
        const int kb = kt * 64;
#pragma unroll
        for (int i = 0; i < 8; i++) {
            int f4  = t + i * 128;
            int row = f4 >> 4;
            int d0  = (f4 & 15) << 2;
            cpa16(&KS[buf * KS_TILE + row * KS_STRIDE + d0],
                  Kp + (size_t)(kb + row) * EMB + d0);
            cpa16(&VS[buf * VS_TILE + row * VS_STRIDE + d0],
                  Vp + (size_t)(kb + row) * EMB + d0);
        }
        if (t < 16) cpa16(&MS[buf * 64 + t * 4], maskp + kb + t * 4);
        cpa_commit();
    };

    // prologue: start tile 0 into buf 0
    load_tile(0, 0);

    // stage Q tile into VS buf1 area (plain stores; data already tf32-rounded)
#pragma unroll
    for (int i = 0; i < 8; i++) {
        int f4  = t + i * 128;
        int row = f4 >> 4;
        int d0  = (f4 & 15) << 2;
        *(float4*)&VS[VS_TILE + row * VS_STRIDE + d0] =
            *(const float4*)(Qp + (size_t)(qbase + row) * EMB + d0);
    }
    __syncthreads();

    unsigned qa[8][4];
    const int qr = warp * 16 + qn;
#pragma unroll
    for (int ks = 0; ks < 8; ks++) {
        qa[ks][0] = __float_as_uint(VS[VS_TILE + qr * VS_STRIDE + ks * 8 + q4]);
        qa[ks][1] = __float_as_uint(VS[VS_TILE + (qr + 8) * VS_STRIDE + ks * 8 + q4]);
        qa[ks][2] = __float_as_uint(VS[VS_TILE + qr * VS_STRIDE + ks * 8 + q4 + 4]);
        qa[ks][3] = __float_as_uint(VS[VS_TILE + (qr + 8) * VS_STRIDE + ks * 8 + q4 + 4]);
    }
    __syncthreads();  // everyone done with VS buf1 before tile-1 cp.async overwrites

    float o[8][4];
#pragma unroll
    for (int i = 0; i < 8; i++) { o[i][0] = o[i][1] = o[i][2] = o[i][3] = 0.f; }
    float mrow0 = -3.0e38f, mrow1 = -3.0e38f;
    float lrow0 = 0.f, lrow1 = 0.f;

    for (int kt = 0; kt < LSEQ / 64; kt++) {
        const int buf = kt & 1;
        if (kt < LSEQ / 64 - 1) {
            load_tile(kt + 1, buf ^ 1);
            asm volatile("cp.async.wait_group 1;\n");
        } else {
            asm volatile("cp.async.wait_group 0;\n");
        }
        __syncthreads();

        const float* Kb = KS + buf * KS_TILE;
        const float* Vb = VS + buf * VS_TILE;
        const int*   Mb = MS + buf * 64;

        // S = Q @ K^T
        float s[8][4];
#pragma unroll
        for (int i = 0; i < 8; i++) { s[i][0] = s[i][1] = s[i][2] = s[i][3] = 0.f; }
#pragma unroll
        for (int ks = 0; ks < 8; ks++) {
#pragma unroll
            for (int nt = 0; nt < 8; nt++) {
                unsigned b0 = __float_as_uint(Kb[(nt * 8 + qn) * KS_STRIDE + ks * 8 + q4]);
                unsigned b1 = __float_as_uint(Kb[(nt * 8 + qn) * KS_STRIDE + ks * 8 + q4 + 4]);
                mma_tf32(s[nt], qa[ks][0], qa[ks][1], qa[ks][2], qa[ks][3], b0, b1);
            }
        }

        // mask then scale by 1/sqrt(E)=1/32 (ref masks before scaling)
        const float scl = 0.03125f;
#pragma unroll
        for (int nt = 0; nt < 8; nt++) {
            int m0 = Mb[nt * 8 + 2 * q4];
            int m1 = Mb[nt * 8 + 2 * q4 + 1];
            s[nt][0] = m0 ? s[nt][0] * scl : -3.125e18f;
            s[nt][1] = m1 ? s[nt][1] * scl : -3.125e18f;
            s[nt][2] = m0 ? s[nt][2] * scl : -3.125e18f;
            s[nt][3] = m1 ? s[nt][3] * scl : -3.125e18f;
        }

        // online softmax (rows qn and qn+8)
        float mx0 = s[0][0], mx1 = s[0][2];
#pragma unroll
        for (int nt = 0; nt < 8; nt++) {
            mx0 = fmaxf(mx0, fmaxf(s[nt][0], s[nt][1]));
            mx1 = fmaxf(mx1, fmaxf(s[nt][2], s[nt][3]));
        }
        mx0 = fmaxf(mx0, __shfl_xor_sync(0xffffffffu, mx0, 1));
        mx0 = fmaxf(mx0, __shfl_xor_sync(0xffffffffu, mx0, 2));
        mx1 = fmaxf(mx1, __shfl_xor_sync(0xffffffffu, mx1, 1));
        mx1 = fmaxf(mx1, __shfl_xor_sync(0xffffffffu, mx1, 2));

        float mn0 = fmaxf(mrow0, mx0);
        float mn1 = fmaxf(mrow1, mx1);
        float c0 = __expf(mrow0 - mn0);
        float c1 = __expf(mrow1 - mn1);
        mrow0 = mn0; mrow1 = mn1;

        float sum0 = 0.f, sum1 = 0.f;
#pragma unroll
        for (int nt = 0; nt < 8; nt++) {
            s[nt][0] = __expf(s[nt][0] - mn0); sum0 += s[nt][0];
            s[nt][1] = __expf(s[nt][1] - mn0); sum0 += s[nt][1];
            s[nt][2] = __expf(s[nt][2] - mn1); sum1 += s[nt][2];
            s[nt][3] = __expf(s[nt][3] - mn1); sum1 += s[nt][3];
        }
        sum0 += __shfl_xor_sync(0xffffffffu, sum0, 1);
        sum0 += __shfl_xor_sync(0xffffffffu, sum0, 2);
        sum1 += __shfl_xor_sync(0xffffffffu, sum1, 1);
        sum1 += __shfl_xor_sync(0xffffffffu, sum1, 2);
        lrow0 = lrow0 * c0 + sum0;
        lrow1 = lrow1 * c1 + sum1;

#pragma unroll
        for (int nt = 0; nt < 8; nt++) {
            o[nt][0] *= c0; o[nt][1] *= c0; o[nt][2] *= c1; o[nt][3] *= c1;
        }

        // O += P @ V. C-frag -> A-frag via quad shuffles (P truncated to tf32).
        const int  sl1 = (lane & 28) | (q4 >> 1);
        const int  sl2 = sl1 + 2;
        const bool hi  = (q4 & 1);
#pragma unroll
        for (int ks = 0; ks < 8; ks++) {
            float u0 = __shfl_sync(0xffffffffu, s[ks][0], sl1);
            float u1 = __shfl_sync(0xffffffffu, s[ks][1], sl1);
            float u2 = __shfl_sync(0xffffffffu, s[ks][2], sl1);
            float u3 = __shfl_sync(0xffffffffu, s[ks][3], sl1);
            float w0 = __shfl_sync(0xffffffffu, s[ks][0], sl2);
            float w1 = __shfl_sync(0xffffffffu, s[ks][1], sl2);
            float w2 = __shfl_sync(0xffffffffu, s[ks][2], sl2);
            float w3 = __shfl_sync(0xffffffffu, s[ks][3], sl2);
            unsigned a0 = __float_as_uint(hi ? u1 : u0);
            unsigned a1 = __float_as_uint(hi ? u3 : u2);
            unsigned a2 = __float_as_uint(hi ? w1 : w0);
            unsigned a3 = __float_as_uint(hi ? w3 : w2);
#pragma unroll
            for (int nt = 0; nt < 8; nt++) {
                unsigned b0 = __float_as_uint(Vb[(ks * 8 + q4) * VS_STRIDE + nt * 8 + qn]);
                unsigned b1 = __float_as_uint(Vb[(ks * 8 + q4 + 4) * VS_STRIDE + nt * 8 + qn]);
                mma_tf32(o[nt], a0, a1, a2, a3, b0, b1);
            }
        }
        __syncthreads();  // all warps done with buf before it is refilled
    }

    const float inv0 = 1.f / lrow0;
    const float inv1 = 1.f / lrow1;
    float* Op = g_ctx + (size_t)(n * LSEQ + qbase) * EMB + h * HD;
    const int row = warp * 16 + qn;
#pragma unroll
    for (int nt = 0; nt < 8; nt++) {
        int col = nt * 8 + 2 * q4;
        float2 v0;
        v0.x = __uint_as_float(f2tf(o[nt][0] * inv0));
        v0.y = __uint_as_float(f2tf(o[nt][1] * inv0));
        *(float2*)(Op + (size_t)row * EMB + col) = v0;
        float2 v1;
        v1.x = __uint_as_float(f2tf(o[nt][2] * inv1));
        v1.y = __uint_as_float(f2tf(o[nt][3] * inv1));
        *(float2*)(Op + (size_t)(row + 8) * EMB + col) = v1;
    }
}

// ---------------- Kernel 3: out = ctx @ Wo^T + bo (tf32 mma, pipelined) ------
// M=4096, N=1024, K=1024. 128x64 tile, 8 warps, K-step 64. grid (16, 32).
#define OG_AS_TILE (128 * 68)   // floats per A stage
#define OG_WS_TILE (64 * 68)    // floats per W stage
#define OG_SMEM_BYTES ((2 * OG_AS_TILE + 2 * OG_WS_TILE) * 4)

__global__ __launch_bounds__(256) void ogemm_kernel(
    const float* __restrict__ Wo, const float* __restrict__ bo, float* __restrict__ out)
{
    extern __shared__ float fsm[];
    float* AS = fsm;                    // [2][128][68]
    float* WS = fsm + 2 * OG_AS_TILE;   // [2][64][68]

    const int t    = threadIdx.x;
    const int warp = t >> 5;
    const int lane = t & 31;
    const int qn   = lane >> 2;
    const int q4   = lane & 3;
    const int mb   = blockIdx.y * 128;
    const int nb   = blockIdx.x * 64;

    auto load_tile = [&](int it, int buf) {
        const int kb = it * 64;
#pragma unroll
        for (int i = 0; i < 8; i++) {
            int f4  = t + i * 256;
            int row = f4 >> 4;           // 0..127
            int d0  = (f4 & 15) << 2;    // 0..60
            cpa16(&AS[buf * OG_AS_TILE + row * 68 + d0],
                  g_ctx + (size_t)(mb + row) * 1024 + kb + d0);
        }
#pragma unroll
        for (int i = 0; i < 4; i++) {
            int f4  = t + i * 256;
            int row = f4 >> 4;           // 0..63
            int d0  = (f4 & 15) << 2;
            cpa16(&WS[buf * OG_WS_TILE + row * 68 + d0],
                  Wo + (size_t)(nb + row) * 1024 + kb + d0);
        }
        cpa_commit();
    };

    load_tile(0, 0);

    float acc[8][4];
#pragma unroll
    for (int i = 0; i < 8; i++) { acc[i][0] = acc[i][1] = acc[i][2] = acc[i][3] = 0.f; }

    const int r = warp * 16 + qn;
    for (int it = 0; it < 16; it++) {
        const int buf = it & 1;
        if (it < 15) {
            load_tile(it + 1, buf ^ 1);
            asm volatile("cp.async.wait_group 1;\n");
        } else {
            asm volatile("cp.async.wait_group 0;\n");
        }
        __syncthreads();

        const float* Ab = AS + buf * OG_AS_TILE;
        const float* Wb = WS + buf * OG_WS_TILE;
#pragma unroll
        for (int ks = 0; ks < 8; ks++) {
            unsigned a0 = __float_as_uint(Ab[r * 68 + ks * 8 + q4]);
            unsigned a1 = __float_as_uint(Ab[(r + 8) * 68 + ks * 8 + q4]);
            unsigned a2 = __float_as_uint(Ab[r * 68 + ks * 8 + q4 + 4]);
            unsigned a3 = __float_as_uint(Ab[(r + 8) * 68 + ks * 8 + q4 + 4]);
#pragma unroll
            for (int nt = 0; nt < 8; nt++) {
                unsigned b0 = __float_as_uint(Wb[(nt * 8 + qn) * 68 + ks * 8 + q4]);
                unsigned b1 = __float_as_uint(Wb[(nt * 8 + qn) * 68 + ks * 8 + q4 + 4]);
                mma_tf32(acc[nt], a0, a1, a2, a3, b0, b1);
            }
        }
        __syncthreads();
    }

#pragma unroll
    for (int nt = 0; nt < 8; nt++) {
        int col = nt * 8 + 2 * q4;
        float b0 = bo[nb + col], b1 = bo[nb + col + 1];
        float2 v0; v0.x = acc[nt][0] + b0; v0.y = acc[nt][1] + b1;
        *(float2*)(out + (size_t)(mb + r) * 1024 + nb + col) = v0;
        float2 v1; v1.x = acc[nt][2] + b0; v1.y = acc[nt][3] + b1;
        *(float2*)(out + (size_t)(mb + r + 8) * 1024 + nb + col) = v1;
    }
}

extern "C" void kernel_launch(void* const* d_in, const int* in_sizes, int n_in,
                              void* d_out, int out_size) {
    const float* values = (const float*)d_in[0];
    const float* key    = (const float*)d_in[1];
    const float* query  = (const float*)d_in[2];
    const int*   mask   = (const int*)d_in[3];
    const float* Wv     = (const float*)d_in[4];
    const float* Wk     = (const float*)d_in[5];
    const float* Wq     = (const float*)d_in[6];
    const float* bq     = (const float*)d_in[7];
    const float* Wo     = (const float*)d_in[8];
    const float* bo     = (const float*)d_in[9];
    float* out = (float*)d_out;

    cudaFuncSetAttribute(flash_kernel, cudaFuncAttributeMaxDynamicSharedMemorySize,
                         FLASH_SMEM_BYTES);
    cudaFuncSetAttribute(ogemm_kernel, cudaFuncAttributeMaxDynamicSharedMemorySize,
                         OG_SMEM_BYTES);

    proj_kernel<<<dim3(NB * LSEQ * NHD / 64, 3), 128>>>(query, key, values, Wq, Wk, Wv, bq);
    flash_kernel<<<dim3(LSEQ / 64, NB * NHD), 128, FLASH_SMEM_BYTES>>>(mask);
    ogemm_kernel<<<dim3(EMB / 64, NB * LSEQ / 128), 256, OG_SMEM_BYTES>>>(Wo, bo, out);
}

// round 8
// speedup vs baseline: 1.3694x; 1.1398x over previous
#include <cuda_runtime.h>

#define NB   2
#define LSEQ 2048
#define EMB  1024
#define NHD  16
#define HD   64

__device__ float g_q[NB * LSEQ * EMB];
__device__ float g_k[NB * LSEQ * EMB];
__device__ float g_v[NB * LSEQ * EMB];
__device__ float g_ctx[NB * LSEQ * EMB];

__device__ __forceinline__ unsigned f2tf(float x) {
    unsigned u;
    asm("cvt.rna.tf32.f32 %0, %1;" : "=r"(u) : "f"(x));
    return u;
}

__device__ __forceinline__ float ex2(float x) {
    float r;
    asm("ex2.approx.ftz.f32 %0, %1;" : "=f"(r) : "f"(x));
    return r;
}

__device__ __forceinline__ void mma_tf32(float* d,
                                         unsigned a0, unsigned a1, unsigned a2, unsigned a3,
                                         unsigned b0, unsigned b1) {
    asm("mma.sync.aligned.m16n8k8.row.col.f32.tf32.tf32.f32 "
        "{%0,%1,%2,%3}, {%4,%5,%6,%7}, {%8,%9}, {%0,%1,%2,%3};\n"
        : "+f"(d[0]), "+f"(d[1]), "+f"(d[2]), "+f"(d[3])
        : "r"(a0), "r"(a1), "r"(a2), "r"(a3), "r"(b0), "r"(b1));
}

__device__ __forceinline__ void cpa16(void* s, const void* g) {
    unsigned sa = (unsigned)__cvta_generic_to_shared(s);
    asm volatile("cp.async.cg.shared.global [%0], [%1], 16;\n"
                 :: "r"(sa), "l"(__cvta_generic_to_global(g)));
}
__device__ __forceinline__ void cpa_commit() { asm volatile("cp.async.commit_group;\n"); }

// ---------------- Kernel 1: per-head projections via tf32 mma ----------------
__global__ __launch_bounds__(128) void proj_kernel(
    const float* __restrict__ xq, const float* __restrict__ xk, const float* __restrict__ xv,
    const float* __restrict__ Wq, const float* __restrict__ Wk, const float* __restrict__ Wv,
    const float* __restrict__ bq)
{
    __shared__ float Xs[64][68];
    __shared__ float Ws2[64][68];

    const int which = blockIdx.y;
    const float* x   = (which == 0) ? xq : (which == 1) ? xk : xv;
    const float* W   = (which == 0) ? Wq : (which == 1) ? Wk : Wv;
    float*       out = (which == 0) ? g_q : (which == 1) ? g_k : g_v;

    const int t    = threadIdx.x;
    const int warp = t >> 5;
    const int lane = t & 31;
    const int qn   = lane >> 2;
    const int q4   = lane & 3;
    const int rb   = blockIdx.x * 64;

#pragma unroll
    for (int i = 0; i < 8; i++) {
        int f4  = t + i * 128;
        int row = f4 >> 4;
        int d0  = (f4 & 15) << 2;
        *(float4*)&Xs[row][d0]  = *(const float4*)(x + (size_t)(rb + row) * 64 + d0);
        *(float4*)&Ws2[row][d0] = *(const float4*)(W + row * 64 + d0);
    }
    __syncthreads();

    float acc[8][4];
#pragma unroll
    for (int i = 0; i < 8; i++) { acc[i][0] = acc[i][1] = acc[i][2] = acc[i][3] = 0.f; }

    const int r = warp * 16 + qn;
#pragma unroll
    for (int ks = 0; ks < 8; ks++) {
        unsigned a0 = __float_as_uint(Xs[r][ks * 8 + q4]);
        unsigned a1 = __float_as_uint(Xs[r + 8][ks * 8 + q4]);
        unsigned a2 = __float_as_uint(Xs[r][ks * 8 + q4 + 4]);
        unsigned a3 = __float_as_uint(Xs[r + 8][ks * 8 + q4 + 4]);
#pragma unroll
        for (int nt = 0; nt < 8; nt++) {
            unsigned b0 = __float_as_uint(Ws2[nt * 8 + qn][ks * 8 + q4]);
            unsigned b1 = __float_as_uint(Ws2[nt * 8 + qn][ks * 8 + q4 + 4]);
            mma_tf32(acc[nt], a0, a1, a2, a3, b0, b1);
        }
    }

#pragma unroll
    for (int nt = 0; nt < 8; nt++) {
        int col = nt * 8 + 2 * q4;
        float b0 = 0.f, b1 = 0.f;
        if (which == 0) { b0 = bq[col]; b1 = bq[col + 1]; }
        float2 v0;
        v0.x = __uint_as_float(f2tf(acc[nt][0] + b0));
        v0.y = __uint_as_float(f2tf(acc[nt][1] + b1));
        *(float2*)(out + (size_t)(rb + r) * 64 + col) = v0;
        float2 v1;
        v1.x = __uint_as_float(f2tf(acc[nt][2] + b0));
        v1.y = __uint_as_float(f2tf(acc[nt][3] + b1));
        *(float2*)(out + (size_t)(rb + r + 8) * 64 + col) = v1;
    }
}

// ---------------- Kernel 2: flash attention (tf32 mma, cp.async pipeline) ----
// grid (L/128, N*H), 256 threads = 8 warps x 16 q-rows. Double-buffered K/V/mask.
#define KS_STRIDE 68
#define VS_STRIDE 72
#define KS_TILE (64 * KS_STRIDE)
#define VS_TILE (64 * VS_STRIDE)
#define FLASH_SMEM_BYTES ((2 * KS_TILE + 2 * VS_TILE) * 4 + 2 * 64 * 4)

__global__ __launch_bounds__(256) void flash_kernel(const int* __restrict__ mask)
{
    extern __shared__ float fsm[];
    float* KS = fsm;                       // [2][64][68]
    float* VS = fsm + 2 * KS_TILE;         // [2][64][72]
    int*   MS = (int*)(fsm + 2 * KS_TILE + 2 * VS_TILE);  // [2][64]

    const int t    = threadIdx.x;
    const int warp = t >> 5;
    const int lane = t & 31;
    const int qn   = lane >> 2;
    const int q4   = lane & 3;

    const int nh = blockIdx.y;
    const int n  = nh >> 4;
    const int h  = nh & 15;
    const int qbase = blockIdx.x * 128;

    const float* Qp = g_q + (size_t)n * LSEQ * EMB + h * HD;
    const float* Kp = g_k + (size_t)n * LSEQ * EMB + h * HD;
    const float* Vp = g_v + (size_t)n * LSEQ * EMB + h * HD;
    const int* maskp = mask + n * LSEQ;

    auto load_tile = [&](int kt, int buf) {
        const int kb = kt * 64;
#pragma unroll
        for (int i = 0; i < 4; i++) {
            int f4  = t + i * 256;
            int row = f4 >> 4;
            int d0  = (f4 & 15) << 2;
            cpa16(&KS[buf * KS_TILE + row * KS_STRIDE + d0],
                  Kp + (size_t)(kb + row) * EMB + d0);
            cpa16(&VS[buf * VS_TILE + row * VS_STRIDE + d0],
                  Vp + (size_t)(kb + row) * EMB + d0);
        }
        if (t < 16) cpa16(&MS[buf * 64 + t * 4], maskp + kb + t * 4);
        cpa_commit();
    };

    // prologue: start tile 0 into buf 0
    load_tile(0, 0);

    // stage 128-row Q tile: rows 0-63 -> KS buf1, rows 64-127 -> VS buf1
#pragma unroll
    for (int i = 0; i < 8; i++) {
        int f4  = t + i * 256;
        int row = f4 >> 4;                 // 0..127
        int d0  = (f4 & 15) << 2;
        const float4 qv = *(const float4*)(Qp + (size_t)(qbase + row) * EMB + d0);
        if (row < 64)
            *(float4*)&KS[KS_TILE + row * KS_STRIDE + d0] = qv;
        else
            *(float4*)&VS[VS_TILE + (row - 64) * VS_STRIDE + d0] = qv;
    }
    __syncthreads();

    unsigned qa[8][4];
    {
        const int qr = warp * 16 + qn;
        const float* Qs;
        int stride, r0;
        if (qr < 64) { Qs = KS + KS_TILE; stride = KS_STRIDE; r0 = qr; }
        else         { Qs = VS + VS_TILE; stride = VS_STRIDE; r0 = qr - 64; }
#pragma unroll
        for (int ks = 0; ks < 8; ks++) {
            qa[ks][0] = __float_as_uint(Qs[r0 * stride + ks * 8 + q4]);
            qa[ks][1] = __float_as_uint(Qs[(r0 + 8) * stride + ks * 8 + q4]);
            qa[ks][2] = __float_as_uint(Qs[r0 * stride + ks * 8 + q4 + 4]);
            qa[ks][3] = __float_as_uint(Qs[(r0 + 8) * stride + ks * 8 + q4 + 4]);
        }
    }
    __syncthreads();  // Q reads done before tile-1 cp.async overwrites buf1

    float o[8][4];
#pragma unroll
    for (int i = 0; i < 8; i++) { o[i][0] = o[i][1] = o[i][2] = o[i][3] = 0.f; }
    float mrow0 = -3.0e38f, mrow1 = -3.0e38f;
    float lrow0 = 0.f, lrow1 = 0.f;

    // logits kept in log2 domain: scale = log2(e)/sqrt(E) = log2(e)/32
    const float scl = 1.4426950408889634f / 32.0f;

    for (int kt = 0; kt < LSEQ / 64; kt++) {
        const int buf = kt & 1;
        if (kt < LSEQ / 64 - 1) {
            load_tile(kt + 1, buf ^ 1);
            asm volatile("cp.async.wait_group 1;\n");
        } else {
            asm volatile("cp.async.wait_group 0;\n");
        }
        __syncthreads();

        const float* Kb = KS + buf * KS_TILE;
        const float* Vb = VS + buf * VS_TILE;
        const int*   Mb = MS + buf * 64;

        // S = Q @ K^T
        float s[8][4];
#pragma unroll
        for (int i = 0; i < 8; i++) { s[i][0] = s[i][1] = s[i][2] = s[i][3] = 0.f; }
#pragma unroll
        for (int ks = 0; ks < 8; ks++) {
#pragma unroll
            for (int nt = 0; nt < 8; nt++) {
                unsigned b0 = __float_as_uint(Kb[(nt * 8 + qn) * KS_STRIDE + ks * 8 + q4]);
                unsigned b1 = __float_as_uint(Kb[(nt * 8 + qn) * KS_STRIDE + ks * 8 + q4 + 4]);
                mma_tf32(s[nt], qa[ks][0], qa[ks][1], qa[ks][2], qa[ks][3], b0, b1);
            }
        }

        // mask then scale (ref masks with -1e20 before dividing by 32; in log2
        // domain the masked value just needs to underflow ex2 -> use -4.5e18)
#pragma unroll
        for (int nt = 0; nt < 8; nt++) {
            int m0 = Mb[nt * 8 + 2 * q4];
            int m1 = Mb[nt * 8 + 2 * q4 + 1];
            s[nt][0] = m0 ? s[nt][0] * scl : -4.5e18f;
            s[nt][1] = m1 ? s[nt][1] * scl : -4.5e18f;
            s[nt][2] = m0 ? s[nt][2] * scl : -4.5e18f;
            s[nt][3] = m1 ? s[nt][3] * scl : -4.5e18f;
        }

        // online softmax in log2 domain (rows qn and qn+8)
        float mx0 = s[0][0], mx1 = s[0][2];
#pragma unroll
        for (int nt = 0; nt < 8; nt++) {
            mx0 = fmaxf(mx0, fmaxf(s[nt][0], s[nt][1]));
            mx1 = fmaxf(mx1, fmaxf(s[nt][2], s[nt][3]));
        }
        mx0 = fmaxf(mx0, __shfl_xor_sync(0xffffffffu, mx0, 1));
        mx0 = fmaxf(mx0, __shfl_xor_sync(0xffffffffu, mx0, 2));
        mx1 = fmaxf(mx1, __shfl_xor_sync(0xffffffffu, mx1, 1));
        mx1 = fmaxf(mx1, __shfl_xor_sync(0xffffffffu, mx1, 2));

        float mn0 = fmaxf(mrow0, mx0);
        float mn1 = fmaxf(mrow1, mx1);
        float c0 = ex2(mrow0 - mn0);
        float c1 = ex2(mrow1 - mn1);
        mrow0 = mn0; mrow1 = mn1;

        float sum0 = 0.f, sum1 = 0.f;
#pragma unroll
        for (int nt = 0; nt < 8; nt++) {
            s[nt][0] = ex2(s[nt][0] - mn0); sum0 += s[nt][0];
            s[nt][1] = ex2(s[nt][1] - mn0); sum0 += s[nt][1];
            s[nt][2] = ex2(s[nt][2] - mn1); sum1 += s[nt][2];
            s[nt][3] = ex2(s[nt][3] - mn1); sum1 += s[nt][3];
        }
        sum0 += __shfl_xor_sync(0xffffffffu, sum0, 1);
        sum0 += __shfl_xor_sync(0xffffffffu, sum0, 2);
        sum1 += __shfl_xor_sync(0xffffffffu, sum1, 1);
        sum1 += __shfl_xor_sync(0xffffffffu, sum1, 2);
        lrow0 = lrow0 * c0 + sum0;
        lrow1 = lrow1 * c1 + sum1;

#pragma unroll
        for (int nt = 0; nt < 8; nt++) {
            o[nt][0] *= c0; o[nt][1] *= c0; o[nt][2] *= c1; o[nt][3] *= c1;
        }

        // O += P @ V. C-frag -> A-frag via quad shuffles (P truncated to tf32).
        const int  sl1 = (lane & 28) | (q4 >> 1);
        const int  sl2 = sl1 + 2;
        const bool hi  = (q4 & 1);
#pragma unroll
        for (int ks = 0; ks < 8; ks++) {
            float u0 = __shfl_sync(0xffffffffu, s[ks][0], sl1);
            float u1 = __shfl_sync(0xffffffffu, s[ks][1], sl1);
            float u2 = __shfl_sync(0xffffffffu, s[ks][2], sl1);
            float u3 = __shfl_sync(0xffffffffu, s[ks][3], sl1);
            float w0 = __shfl_sync(0xffffffffu, s[ks][0], sl2);
            float w1 = __shfl_sync(0xffffffffu, s[ks][1], sl2);
            float w2 = __shfl_sync(0xffffffffu, s[ks][2], sl2);
            float w3 = __shfl_sync(0xffffffffu, s[ks][3], sl2);
            unsigned a0 = __float_as_uint(hi ? u1 : u0);
            unsigned a1 = __float_as_uint(hi ? u3 : u2);
            unsigned a2 = __float_as_uint(hi ? w1 : w0);
            unsigned a3 = __float_as_uint(hi ? w3 : w2);
#pragma unroll
            for (int nt = 0; nt < 8; nt++) {
                unsigned b0 = __float_as_uint(Vb[(ks * 8 + q4) * VS_STRIDE + nt * 8 + qn]);
                unsigned b1 = __float_as_uint(Vb[(ks * 8 + q4 + 4) * VS_STRIDE + nt * 8 + qn]);
                mma_tf32(o[nt], a0, a1, a2, a3, b0, b1);
            }
        }
        __syncthreads();  // all warps done with buf before it is refilled
    }

    const float inv0 = 1.f / lrow0;
    const float inv1 = 1.f / lrow1;
    float* Op = g_ctx + (size_t)(n * LSEQ + qbase) * EMB + h * HD;
    const int row = warp * 16 + qn;
#pragma unroll
    for (int nt = 0; nt < 8; nt++) {
        int col = nt * 8 + 2 * q4;
        float2 v0;
        v0.x = __uint_as_float(f2tf(o[nt][0] * inv0));
        v0.y = __uint_as_float(f2tf(o[nt][1] * inv0));
        *(float2*)(Op + (size_t)row * EMB + col) = v0;
        float2 v1;
        v1.x = __uint_as_float(f2tf(o[nt][2] * inv1));
        v1.y = __uint_as_float(f2tf(o[nt][3] * inv1));
        *(float2*)(Op + (size_t)(row + 8) * EMB + col) = v1;
    }
}

// ---------------- Kernel 3: out = ctx @ Wo^T + bo (tf32 mma, pipelined) ------
#define OG_AS_TILE (128 * 68)
#define OG_WS_TILE (64 * 68)
#define OG_SMEM_BYTES ((2 * OG_AS_TILE + 2 * OG_WS_TILE) * 4)

__global__ __launch_bounds__(256) void ogemm_kernel(
    const float* __restrict__ Wo, const float* __restrict__ bo, float* __restrict__ out)
{
    extern __shared__ float fsm[];
    float* AS = fsm;                    // [2][128][68]
    float* WS = fsm + 2 * OG_AS_TILE;   // [2][64][68]

    const int t    = threadIdx.x;
    const int warp = t >> 5;
    const int lane = t & 31;
    const int qn   = lane >> 2;
    const int q4   = lane & 3;
    const int mb   = blockIdx.y * 128;
    const int nb   = blockIdx.x * 64;

    auto load_tile = [&](int it, int buf) {
        const int kb = it * 64;
#pragma unroll
        for (int i = 0; i < 8; i++) {
            int f4  = t + i * 256;
            int row = f4 >> 4;
            int d0  = (f4 & 15) << 2;
            cpa16(&AS[buf * OG_AS_TILE + row * 68 + d0],
                  g_ctx + (size_t)(mb + row) * 1024 + kb + d0);
        }
#pragma unroll
        for (int i = 0; i < 4; i++) {
            int f4  = t + i * 256;
            int row = f4 >> 4;
            int d0  = (f4 & 15) << 2;
            cpa16(&WS[buf * OG_WS_TILE + row * 68 + d0],
                  Wo + (size_t)(nb + row) * 1024 + kb + d0);
        }
        cpa_commit();
    };

    load_tile(0, 0);

    float acc[8][4];
#pragma unroll
    for (int i = 0; i < 8; i++) { acc[i][0] = acc[i][1] = acc[i][2] = acc[i][3] = 0.f; }

    const int r = warp * 16 + qn;
    for (int it = 0; it < 16; it++) {
        const int buf = it & 1;
        if (it < 15) {
            load_tile(it + 1, buf ^ 1);
            asm volatile("cp.async.wait_group 1;\n");
        } else {
            asm volatile("cp.async.wait_group 0;\n");
        }
        __syncthreads();

        const float* Ab = AS + buf * OG_AS_TILE;
        const float* Wb = WS + buf * OG_WS_TILE;
#pragma unroll
        for (int ks = 0; ks < 8; ks++) {
            unsigned a0 = __float_as_uint(Ab[r * 68 + ks * 8 + q4]);
            unsigned a1 = __float_as_uint(Ab[(r + 8) * 68 + ks * 8 + q4]);
            unsigned a2 = __float_as_uint(Ab[r * 68 + ks * 8 + q4 + 4]);
            unsigned a3 = __float_as_uint(Ab[(r + 8) * 68 + ks * 8 + q4 + 4]);
#pragma unroll
            for (int nt = 0; nt < 8; nt++) {
                unsigned b0 = __float_as_uint(Wb[(nt * 8 + qn) * 68 + ks * 8 + q4]);
                unsigned b1 = __float_as_uint(Wb[(nt * 8 + qn) * 68 + ks * 8 + q4 + 4]);
                mma_tf32(acc[nt], a0, a1, a2, a3, b0, b1);
            }
        }
        __syncthreads();
    }

#pragma unroll
    for (int nt = 0; nt < 8; nt++) {
        int col = nt * 8 + 2 * q4;
        float b0 = bo[nb + col], b1 = bo[nb + col + 1];
        float2 v0; v0.x = acc[nt][0] + b0; v0.y = acc[nt][1] + b1;
        *(float2*)(out + (size_t)(mb + r) * 1024 + nb + col) = v0;
        float2 v1; v1.x = acc[nt][2] + b0; v1.y = acc[nt][3] + b1;
        *(float2*)(out + (size_t)(mb + r + 8) * 1024 + nb + col) = v1;
    }
}

extern "C" void kernel_launch(void* const* d_in, const int* in_sizes, int n_in,
                              void* d_out, int out_size) {
    const float* values = (const float*)d_in[0];
    const float* key    = (const float*)d_in[1];
    const float* query  = (const float*)d_in[2];
    const int*   mask   = (const int*)d_in[3];
    const float* Wv     = (const float*)d_in[4];
    const float* Wk     = (const float*)d_in[5];
    const float* Wq     = (const float*)d_in[6];
    const float* bq     = (const float*)d_in[7];
    const float* Wo     = (const float*)d_in[8];
    const float* bo     = (const float*)d_in[9];
    float* out = (float*)d_out;

    cudaFuncSetAttribute(flash_kernel, cudaFuncAttributeMaxDynamicSharedMemorySize,
                         FLASH_SMEM_BYTES);
    cudaFuncSetAttribute(ogemm_kernel, cudaFuncAttributeMaxDynamicSharedMemorySize,
                         OG_SMEM_BYTES);

    proj_kernel<<<dim3(NB * LSEQ * NHD / 64, 3), 128>>>(query, key, values, Wq, Wk, Wv, bq);
    flash_kernel<<<dim3(LSEQ / 128, NB * NHD), 256, FLASH_SMEM_BYTES>>>(mask);
    ogemm_kernel<<<dim3(EMB / 64, NB * LSEQ / 128), 256, OG_SMEM_BYTES>>>(Wo, bo, out);
}

// round 9
// speedup vs baseline: 1.6433x; 1.2000x over previous
#include <cuda_runtime.h>

#define NB   2
#define LSEQ 2048
#define EMB  1024
#define NHD  16
#define HD   64

__device__ unsigned short g_qh[NB * LSEQ * EMB];  // bf16
__device__ unsigned short g_kh[NB * LSEQ * EMB];  // bf16
__device__ float g_v[NB * LSEQ * EMB];
__device__ float g_ctx[NB * LSEQ * EMB];

__device__ __forceinline__ unsigned f2tf(float x) {
    unsigned u;
    asm("cvt.rna.tf32.f32 %0, %1;" : "=r"(u) : "f"(x));
    return u;
}

__device__ __forceinline__ unsigned pack_bf16(float lo, float hi) {
    unsigned r;
    asm("cvt.rn.bf16x2.f32 %0, %1, %2;" : "=r"(r) : "f"(hi), "f"(lo));
    return r;
}

__device__ __forceinline__ float ex2(float x) {
    float r;
    asm("ex2.approx.ftz.f32 %0, %1;" : "=f"(r) : "f"(x));
    return r;
}

__device__ __forceinline__ void mma_tf32(float* d,
                                         unsigned a0, unsigned a1, unsigned a2, unsigned a3,
                                         unsigned b0, unsigned b1) {
    asm("mma.sync.aligned.m16n8k8.row.col.f32.tf32.tf32.f32 "
        "{%0,%1,%2,%3}, {%4,%5,%6,%7}, {%8,%9}, {%0,%1,%2,%3};\n"
        : "+f"(d[0]), "+f"(d[1]), "+f"(d[2]), "+f"(d[3])
        : "r"(a0), "r"(a1), "r"(a2), "r"(a3), "r"(b0), "r"(b1));
}

__device__ __forceinline__ void mma_bf16(float* d,
                                         unsigned a0, unsigned a1, unsigned a2, unsigned a3,
                                         unsigned b0, unsigned b1) {
    asm("mma.sync.aligned.m16n8k16.row.col.f32.bf16.bf16.f32 "
        "{%0,%1,%2,%3}, {%4,%5,%6,%7}, {%8,%9}, {%0,%1,%2,%3};\n"
        : "+f"(d[0]), "+f"(d[1]), "+f"(d[2]), "+f"(d[3])
        : "r"(a0), "r"(a1), "r"(a2), "r"(a3), "r"(b0), "r"(b1));
}

__device__ __forceinline__ void cpa16(void* s, const void* g) {
    unsigned sa = (unsigned)__cvta_generic_to_shared(s);
    asm volatile("cp.async.cg.shared.global [%0], [%1], 16;\n"
                 :: "r"(sa), "l"(__cvta_generic_to_global(g)));
}
__device__ __forceinline__ void cpa_commit() { asm volatile("cp.async.commit_group;\n"); }

// ---------------- Kernel 1: per-head projections via tf32 mma ----------------
// q,k written as bf16; v written tf32-rounded fp32.
__global__ __launch_bounds__(128) void proj_kernel(
    const float* __restrict__ xq, const float* __restrict__ xk, const float* __restrict__ xv,
    const float* __restrict__ Wq, const float* __restrict__ Wk, const float* __restrict__ Wv,
    const float* __restrict__ bq)
{
    __shared__ float Xs[64][68];
    __shared__ float Ws2[64][68];

    const int which = blockIdx.y;
    const float* x = (which == 0) ? xq : (which == 1) ? xk : xv;
    const float* W = (which == 0) ? Wq : (which == 1) ? Wk : Wv;

    const int t    = threadIdx.x;
    const int warp = t >> 5;
    const int lane = t & 31;
    const int qn   = lane >> 2;
    const int q4   = lane & 3;
    const int rb   = blockIdx.x * 64;

#pragma unroll
    for (int i = 0; i < 8; i++) {
        int f4  = t + i * 128;
        int row = f4 >> 4;
        int d0  = (f4 & 15) << 2;
        *(float4*)&Xs[row][d0]  = *(const float4*)(x + (size_t)(rb + row) * 64 + d0);
        *(float4*)&Ws2[row][d0] = *(const float4*)(W + row * 64 + d0);
    }
    __syncthreads();

    float acc[8][4];
#pragma unroll
    for (int i = 0; i < 8; i++) { acc[i][0] = acc[i][1] = acc[i][2] = acc[i][3] = 0.f; }

    const int r = warp * 16 + qn;
#pragma unroll
    for (int ks = 0; ks < 8; ks++) {
        unsigned a0 = __float_as_uint(Xs[r][ks * 8 + q4]);
        unsigned a1 = __float_as_uint(Xs[r + 8][ks * 8 + q4]);
        unsigned a2 = __float_as_uint(Xs[r][ks * 8 + q4 + 4]);
        unsigned a3 = __float_as_uint(Xs[r + 8][ks * 8 + q4 + 4]);
#pragma unroll
        for (int nt = 0; nt < 8; nt++) {
            unsigned b0 = __float_as_uint(Ws2[nt * 8 + qn][ks * 8 + q4]);
            unsigned b1 = __float_as_uint(Ws2[nt * 8 + qn][ks * 8 + q4 + 4]);
            mma_tf32(acc[nt], a0, a1, a2, a3, b0, b1);
        }
    }

    if (which == 2) {
#pragma unroll
        for (int nt = 0; nt < 8; nt++) {
            int col = nt * 8 + 2 * q4;
            float2 v0;
            v0.x = __uint_as_float(f2tf(acc[nt][0]));
            v0.y = __uint_as_float(f2tf(acc[nt][1]));
            *(float2*)(g_v + (size_t)(rb + r) * 64 + col) = v0;
            float2 v1;
            v1.x = __uint_as_float(f2tf(acc[nt][2]));
            v1.y = __uint_as_float(f2tf(acc[nt][3]));
            *(float2*)(g_v + (size_t)(rb + r + 8) * 64 + col) = v1;
        }
    } else {
        unsigned short* outh = (which == 0) ? g_qh : g_kh;
#pragma unroll
        for (int nt = 0; nt < 8; nt++) {
            int col = nt * 8 + 2 * q4;
            float b0 = 0.f, b1 = 0.f;
            if (which == 0) { b0 = bq[col]; b1 = bq[col + 1]; }
            unsigned p0 = pack_bf16(acc[nt][0] + b0, acc[nt][1] + b1);
            *(unsigned*)(outh + (size_t)(rb + r) * 64 + col) = p0;
            unsigned p1 = pack_bf16(acc[nt][2] + b0, acc[nt][3] + b1);
            *(unsigned*)(outh + (size_t)(rb + r + 8) * 64 + col) = p1;
        }
    }
}

// ---------------- Kernel 2: flash attention (bf16 QK, tf32 PV) --------------
// grid (L/128, N*H), 256 threads = 8 warps x 16 q-rows. Double-buffered K/V/mask.
#define KH_STRIDE 36                 // u32 per bf16 K row (72 bf16)
#define KH_TILE  (64 * KH_STRIDE)    // u32 per K stage
#define VSF_STRIDE 72
#define VSF_TILE (64 * VSF_STRIDE)   // f32 per V stage
#define FLASH_SMEM_BYTES (2 * KH_TILE * 4 + 2 * VSF_TILE * 4 + 2 * 64 * 4)

__global__ __launch_bounds__(256) void flash_kernel(const int* __restrict__ mask)
{
    extern __shared__ unsigned char smraw[];
    unsigned* KSu = (unsigned*)smraw;                         // [2][64][36] u32 (bf16x2)
    float*    VS  = (float*)(smraw + 2 * KH_TILE * 4);        // [2][64][72] f32
    int*      MS  = (int*)(smraw + 2 * KH_TILE * 4 + 2 * VSF_TILE * 4);  // [2][64]

    const int t    = threadIdx.x;
    const int warp = t >> 5;
    const int lane = t & 31;
    const int qn   = lane >> 2;
    const int q4   = lane & 3;

    const int nh = blockIdx.y;
    const int n  = nh >> 4;
    const int h  = nh & 15;
    const int qbase = blockIdx.x * 128;

    const unsigned short* Qp = g_qh + (size_t)n * LSEQ * EMB + h * HD;
    const unsigned short* Kp = g_kh + (size_t)n * LSEQ * EMB + h * HD;
    const float*          Vp = g_v  + (size_t)n * LSEQ * EMB + h * HD;
    const int* maskp = mask + n * LSEQ;

    auto load_tile = [&](int kt, int buf) {
        const int kb = kt * 64;
        // K: 64 rows x 128B (bf16) = 512 x 16B chunks
#pragma unroll
        for (int i = 0; i < 2; i++) {
            int idx = t + i * 256;
            int row = idx >> 3;
            int c   = idx & 7;
            cpa16(&KSu[buf * KH_TILE + row * KH_STRIDE + c * 4],
                  Kp + (size_t)(kb + row) * EMB + c * 8);
        }
        // V: 64 rows x 256B (f32) = 1024 x 16B chunks
#pragma unroll
        for (int i = 0; i < 4; i++) {
            int idx = t + i * 256;
            int row = idx >> 4;
            int c   = idx & 15;
            cpa16(&VS[buf * VSF_TILE + row * VSF_STRIDE + c * 4],
                  Vp + (size_t)(kb + row) * EMB + c * 4);
        }
        if (t < 16) cpa16(&MS[buf * 64 + t * 4], maskp + kb + t * 4);
        cpa_commit();
    };

    load_tile(0, 0);

    // Q A-fragments (bf16, m16n8k16): direct global loads, 16 u32/thread
    unsigned qa[4][4];
    const int qr = warp * 16 + qn;
#pragma unroll
    for (int ks = 0; ks < 4; ks++) {
        size_t base = (size_t)(qbase + qr) * EMB + ks * 16 + 2 * q4;
        qa[ks][0] = *(const unsigned*)(Qp + base);
        qa[ks][1] = *(const unsigned*)(Qp + base + (size_t)8 * EMB);
        qa[ks][2] = *(const unsigned*)(Qp + base + 8);
        qa[ks][3] = *(const unsigned*)(Qp + base + (size_t)8 * EMB + 8);
    }

    float o[8][4];
#pragma unroll
    for (int i = 0; i < 8; i++) { o[i][0] = o[i][1] = o[i][2] = o[i][3] = 0.f; }
    float mrow0 = -3.0e38f, mrow1 = -3.0e38f;
    float lrow0 = 0.f, lrow1 = 0.f;

    // log2-domain scale: log2(e)/sqrt(E)
    const float scl = 1.4426950408889634f / 32.0f;

    for (int kt = 0; kt < LSEQ / 64; kt++) {
        const int buf = kt & 1;
        if (kt < LSEQ / 64 - 1) {
            load_tile(kt + 1, buf ^ 1);
            asm volatile("cp.async.wait_group 1;\n");
        } else {
            asm volatile("cp.async.wait_group 0;\n");
        }
        __syncthreads();

        const unsigned* Kb = KSu + buf * KH_TILE;
        const float*    Vb = VS + buf * VSF_TILE;
        const int*      Mb = MS + buf * 64;

        // S = Q @ K^T (bf16 k16)
        float s[8][4];
#pragma unroll
        for (int i = 0; i < 8; i++) { s[i][0] = s[i][1] = s[i][2] = s[i][3] = 0.f; }
#pragma unroll
        for (int ks = 0; ks < 4; ks++) {
#pragma unroll
            for (int nt = 0; nt < 8; nt++) {
                const unsigned* Krow = Kb + (nt * 8 + qn) * KH_STRIDE + ks * 8 + q4;
                mma_bf16(s[nt], qa[ks][0], qa[ks][1], qa[ks][2], qa[ks][3],
                         Krow[0], Krow[4]);
            }
        }

        // mask then scale (masked -> underflow ex2)
#pragma unroll
        for (int nt = 0; nt < 8; nt++) {
            int m0 = Mb[nt * 8 + 2 * q4];
            int m1 = Mb[nt * 8 + 2 * q4 + 1];
            s[nt][0] = m0 ? s[nt][0] * scl : -4.5e18f;
            s[nt][1] = m1 ? s[nt][1] * scl : -4.5e18f;
            s[nt][2] = m0 ? s[nt][2] * scl : -4.5e18f;
            s[nt][3] = m1 ? s[nt][3] * scl : -4.5e18f;
        }

        // online softmax (log2 domain), rows qn and qn+8
        float mx0 = s[0][0], mx1 = s[0][2];
#pragma unroll
        for (int nt = 0; nt < 8; nt++) {
            mx0 = fmaxf(mx0, fmaxf(s[nt][0], s[nt][1]));
            mx1 = fmaxf(mx1, fmaxf(s[nt][2], s[nt][3]));
        }
        mx0 = fmaxf(mx0, __shfl_xor_sync(0xffffffffu, mx0, 1));
        mx0 = fmaxf(mx0, __shfl_xor_sync(0xffffffffu, mx0, 2));
        mx1 = fmaxf(mx1, __shfl_xor_sync(0xffffffffu, mx1, 1));
        mx1 = fmaxf(mx1, __shfl_xor_sync(0xffffffffu, mx1, 2));

        float mn0 = fmaxf(mrow0, mx0);
        float mn1 = fmaxf(mrow1, mx1);
        float c0 = ex2(mrow0 - mn0);
        float c1 = ex2(mrow1 - mn1);
        mrow0 = mn0; mrow1 = mn1;

        float sum0 = 0.f, sum1 = 0.f;
#pragma unroll
        for (int nt = 0; nt < 8; nt++) {
            s[nt][0] = ex2(s[nt][0] - mn0); sum0 += s[nt][0];
            s[nt][1] = ex2(s[nt][1] - mn0); sum0 += s[nt][1];
            s[nt][2] = ex2(s[nt][2] - mn1); sum1 += s[nt][2];
            s[nt][3] = ex2(s[nt][3] - mn1); sum1 += s[nt][3];
        }
        sum0 += __shfl_xor_sync(0xffffffffu, sum0, 1);
        sum0 += __shfl_xor_sync(0xffffffffu, sum0, 2);
        sum1 += __shfl_xor_sync(0xffffffffu, sum1, 1);
        sum1 += __shfl_xor_sync(0xffffffffu, sum1, 2);
        lrow0 = lrow0 * c0 + sum0;
        lrow1 = lrow1 * c1 + sum1;

#pragma unroll
        for (int nt = 0; nt < 8; nt++) {
            o[nt][0] *= c0; o[nt][1] *= c0; o[nt][2] *= c1; o[nt][3] *= c1;
        }

        // O += P @ V (tf32). C-frag -> A-frag via quad shuffles.
        const int  sl1 = (lane & 28) | (q4 >> 1);
        const int  sl2 = sl1 + 2;
        const bool hi  = (q4 & 1);
#pragma unroll
        for (int ks = 0; ks < 8; ks++) {
            float u0 = __shfl_sync(0xffffffffu, s[ks][0], sl1);
            float u1 = __shfl_sync(0xffffffffu, s[ks][1], sl1);
            float u2 = __shfl_sync(0xffffffffu, s[ks][2], sl1);
            float u3 = __shfl_sync(0xffffffffu, s[ks][3], sl1);
            float w0 = __shfl_sync(0xffffffffu, s[ks][0], sl2);
            float w1 = __shfl_sync(0xffffffffu, s[ks][1], sl2);
            float w2 = __shfl_sync(0xffffffffu, s[ks][2], sl2);
            float w3 = __shfl_sync(0xffffffffu, s[ks][3], sl2);
            unsigned a0 = __float_as_uint(hi ? u1 : u0);
            unsigned a1 = __float_as_uint(hi ? u3 : u2);
            unsigned a2 = __float_as_uint(hi ? w1 : w0);
            unsigned a3 = __float_as_uint(hi ? w3 : w2);
#pragma unroll
            for (int nt = 0; nt < 8; nt++) {
                unsigned b0 = __float_as_uint(Vb[(ks * 8 + q4) * VSF_STRIDE + nt * 8 + qn]);
                unsigned b1 = __float_as_uint(Vb[(ks * 8 + q4 + 4) * VSF_STRIDE + nt * 8 + qn]);
                mma_tf32(o[nt], a0, a1, a2, a3, b0, b1);
            }
        }
        __syncthreads();
    }

    const float inv0 = 1.f / lrow0;
    const float inv1 = 1.f / lrow1;
    float* Op = g_ctx + (size_t)(n * LSEQ + qbase) * EMB + h * HD;
    const int row = warp * 16 + qn;
#pragma unroll
    for (int nt = 0; nt < 8; nt++) {
        int col = nt * 8 + 2 * q4;
        float2 v0;
        v0.x = __uint_as_float(f2tf(o[nt][0] * inv0));
        v0.y = __uint_as_float(f2tf(o[nt][1] * inv0));
        *(float2*)(Op + (size_t)row * EMB + col) = v0;
        float2 v1;
        v1.x = __uint_as_float(f2tf(o[nt][2] * inv1));
        v1.y = __uint_as_float(f2tf(o[nt][3] * inv1));
        *(float2*)(Op + (size_t)(row + 8) * EMB + col) = v1;
    }
}

// ---------------- Kernel 3: out = ctx @ Wo^T + bo (tf32 mma, K-step 32) ------
#define OG_AS_TILE (128 * 36)
#define OG_WS_TILE (64 * 36)
#define OG_SMEM_BYTES ((2 * OG_AS_TILE + 2 * OG_WS_TILE) * 4)

__global__ __launch_bounds__(256) void ogemm_kernel(
    const float* __restrict__ Wo, const float* __restrict__ bo, float* __restrict__ out)
{
    extern __shared__ float fsm[];
    float* AS = fsm;                    // [2][128][36]
    float* WS = fsm + 2 * OG_AS_TILE;   // [2][64][36]

    const int t    = threadIdx.x;
    const int warp = t >> 5;
    const int lane = t & 31;
    const int qn   = lane >> 2;
    const int q4   = lane & 3;
    const int mb   = blockIdx.y * 128;
    const int nb   = blockIdx.x * 64;

    auto load_tile = [&](int it, int buf) {
        const int kb = it * 32;
#pragma unroll
        for (int i = 0; i < 4; i++) {
            int idx = t + i * 256;
            int row = idx >> 3;          // 0..127
            int c   = idx & 7;
            cpa16(&AS[buf * OG_AS_TILE + row * 36 + c * 4],
                  g_ctx + (size_t)(mb + row) * 1024 + kb + c * 4);
        }
#pragma unroll
        for (int i = 0; i < 2; i++) {
            int idx = t + i * 256;
            int row = idx >> 3;          // 0..63
            int c   = idx & 7;
            cpa16(&WS[buf * OG_WS_TILE + row * 36 + c * 4],
                  Wo + (size_t)(nb + row) * 1024 + kb + c * 4);
        }
        cpa_commit();
    };

    load_tile(0, 0);

    float acc[8][4];
#pragma unroll
    for (int i = 0; i < 8; i++) { acc[i][0] = acc[i][1] = acc[i][2] = acc[i][3] = 0.f; }

    const int r = warp * 16 + qn;
    for (int it = 0; it < 32; it++) {
        const int buf = it & 1;
        if (it < 31) {
            load_tile(it + 1, buf ^ 1);
            asm volatile("cp.async.wait_group 1;\n");
        } else {
            asm volatile("cp.async.wait_group 0;\n");
        }
        __syncthreads();

        const float* Ab = AS + buf * OG_AS_TILE;
        const float* Wb = WS + buf * OG_WS_TILE;
#pragma unroll
        for (int ks = 0; ks < 4; ks++) {
            unsigned a0 = __float_as_uint(Ab[r * 36 + ks * 8 + q4]);
            unsigned a1 = __float_as_uint(Ab[(r + 8) * 36 + ks * 8 + q4]);
            unsigned a2 = __float_as_uint(Ab[r * 36 + ks * 8 + q4 + 4]);
            unsigned a3 = __float_as_uint(Ab[(r + 8) * 36 + ks * 8 + q4 + 4]);
#pragma unroll
            for (int nt = 0; nt < 8; nt++) {
                unsigned b0 = __float_as_uint(Wb[(nt * 8 + qn) * 36 + ks * 8 + q4]);
                unsigned b1 = __float_as_uint(Wb[(nt * 8 + qn) * 36 + ks * 8 + q4 + 4]);
                mma_tf32(acc[nt], a0, a1, a2, a3, b0, b1);
            }
        }
        __syncthreads();
    }

#pragma unroll
    for (int nt = 0; nt < 8; nt++) {
        int col = nt * 8 + 2 * q4;
        float b0 = bo[nb + col], b1 = bo[nb + col + 1];
        float2 v0; v0.x = acc[nt][0] + b0; v0.y = acc[nt][1] + b1;
        *(float2*)(out + (size_t)(mb + r) * 1024 + nb + col) = v0;
        float2 v1; v1.x = acc[nt][2] + b0; v1.y = acc[nt][3] + b1;
        *(float2*)(out + (size_t)(mb + r + 8) * 1024 + nb + col) = v1;
    }
}

extern "C" void kernel_launch(void* const* d_in, const int* in_sizes, int n_in,
                              void* d_out, int out_size) {
    const float* values = (const float*)d_in[0];
    const float* key    = (const float*)d_in[1];
    const float* query  = (const float*)d_in[2];
    const int*   mask   = (const int*)d_in[3];
    const float* Wv     = (const float*)d_in[4];
    const float* Wk     = (const float*)d_in[5];
    const float* Wq     = (const float*)d_in[6];
    const float* bq     = (const float*)d_in[7];
    const float* Wo     = (const float*)d_in[8];
    const float* bo     = (const float*)d_in[9];
    float* out = (float*)d_out;

    cudaFuncSetAttribute(flash_kernel, cudaFuncAttributeMaxDynamicSharedMemorySize,
                         FLASH_SMEM_BYTES);
    cudaFuncSetAttribute(ogemm_kernel, cudaFuncAttributeMaxDynamicSharedMemorySize,
                         OG_SMEM_BYTES);

    proj_kernel<<<dim3(NB * LSEQ * NHD / 64, 3), 128>>>(query, key, values, Wq, Wk, Wv, bq);
    flash_kernel<<<dim3(LSEQ / 128, NB * NHD), 256, FLASH_SMEM_BYTES>>>(mask);
    ogemm_kernel<<<dim3(EMB / 64, NB * LSEQ / 128), 256, OG_SMEM_BYTES>>>(Wo, bo, out);
}

// round 10
// speedup vs baseline: 2.1648x; 1.3173x over previous
#include <cuda_runtime.h>

#define NB   2
#define LSEQ 2048
#define EMB  1024
#define NHD  16
#define HD   64

__device__ unsigned short g_qh[NB * LSEQ * EMB];       // bf16 Q, (n,l,h,d)
__device__ unsigned short g_kh[NB * LSEQ * EMB];       // bf16 K, (n,l,h,d)
__device__ unsigned g_vt[NB * NHD * HD * (LSEQ / 2)];  // bf16x2 V^T: [(n*16+h)*64+d][l/2]
__device__ float g_ctx[NB * LSEQ * EMB];

__device__ __forceinline__ unsigned f2tf(float x) {
    unsigned u;
    asm("cvt.rna.tf32.f32 %0, %1;" : "=r"(u) : "f"(x));
    return u;
}

// returns {hi:16, lo:16} with lo in the low half
__device__ __forceinline__ unsigned pack_bf16(float lo, float hi) {
    unsigned r;
    asm("cvt.rn.bf16x2.f32 %0, %1, %2;" : "=r"(r) : "f"(hi), "f"(lo));
    return r;
}

__device__ __forceinline__ float ex2(float x) {
    float r;
    asm("ex2.approx.ftz.f32 %0, %1;" : "=f"(r) : "f"(x));
    return r;
}

__device__ __forceinline__ void mma_tf32(float* d,
                                         unsigned a0, unsigned a1, unsigned a2, unsigned a3,
                                         unsigned b0, unsigned b1) {
    asm("mma.sync.aligned.m16n8k8.row.col.f32.tf32.tf32.f32 "
        "{%0,%1,%2,%3}, {%4,%5,%6,%7}, {%8,%9}, {%0,%1,%2,%3};\n"
        : "+f"(d[0]), "+f"(d[1]), "+f"(d[2]), "+f"(d[3])
        : "r"(a0), "r"(a1), "r"(a2), "r"(a3), "r"(b0), "r"(b1));
}

__device__ __forceinline__ void mma_bf16(float* d,
                                         unsigned a0, unsigned a1, unsigned a2, unsigned a3,
                                         unsigned b0, unsigned b1) {
    asm("mma.sync.aligned.m16n8k16.row.col.f32.bf16.bf16.f32 "
        "{%0,%1,%2,%3}, {%4,%5,%6,%7}, {%8,%9}, {%0,%1,%2,%3};\n"
        : "+f"(d[0]), "+f"(d[1]), "+f"(d[2]), "+f"(d[3])
        : "r"(a0), "r"(a1), "r"(a2), "r"(a3), "r"(b0), "r"(b1));
}

__device__ __forceinline__ void cpa16(void* s, const void* g) {
    unsigned sa = (unsigned)__cvta_generic_to_shared(s);
    asm volatile("cp.async.cg.shared.global [%0], [%1], 16;\n"
                 :: "r"(sa), "l"(__cvta_generic_to_global(g)));
}
__device__ __forceinline__ void cpa_commit() { asm volatile("cp.async.commit_group;\n"); }

// ---------------- Kernel 1: per-head projections via tf32 mma ----------------
// which 0: Q -> bf16 row-major. 1: K -> bf16 row-major.
// 2: V -> bf16 TRANSPOSED g_vt[(n*16+h)*64+d][l] (per-(n,h) l-tiles of 64).
__global__ __launch_bounds__(128) void proj_kernel(
    const float* __restrict__ xq, const float* __restrict__ xk, const float* __restrict__ xv,
    const float* __restrict__ Wq, const float* __restrict__ Wk, const float* __restrict__ Wv,
    const float* __restrict__ bq)
{
    __shared__ float Xs[64][68];
    __shared__ float Ws2[64][68];

    const int which = blockIdx.y;
    const float* x = (which == 0) ? xq : (which == 1) ? xk : xv;
    const float* W = (which == 0) ? Wq : (which == 1) ? Wk : Wv;

    const int t    = threadIdx.x;
    const int warp = t >> 5;
    const int lane = t & 31;
    const int qn   = lane >> 2;
    const int q4   = lane & 3;

    // V decode: block -> (n, h, l-tile); Q/K: dense 64-row tiles
    int vn = 0, vh = 0, vl0 = 0;
    if (which == 2) {
        int b = blockIdx.x;
        vn  = b / (NHD * (LSEQ / 64));
        int rem = b % (NHD * (LSEQ / 64));
        vh  = rem / (LSEQ / 64);
        vl0 = (rem % (LSEQ / 64)) * 64;
    }
    const int rb = blockIdx.x * 64;

#pragma unroll
    for (int i = 0; i < 8; i++) {
        int f4  = t + i * 128;
        int row = f4 >> 4;
        int d0  = (f4 & 15) << 2;
        if (which == 2) {
            *(float4*)&Xs[row][d0] =
                *(const float4*)(x + ((size_t)(vn * LSEQ + vl0 + row)) * EMB + vh * HD + d0);
        } else {
            *(float4*)&Xs[row][d0] = *(const float4*)(x + (size_t)(rb + row) * 64 + d0);
        }
        *(float4*)&Ws2[row][d0] = *(const float4*)(W + row * 64 + d0);
    }
    __syncthreads();

    float acc[8][4];
#pragma unroll
    for (int i = 0; i < 8; i++) { acc[i][0] = acc[i][1] = acc[i][2] = acc[i][3] = 0.f; }

    const int r = warp * 16 + qn;
#pragma unroll
    for (int ks = 0; ks < 8; ks++) {
        unsigned a0 = __float_as_uint(Xs[r][ks * 8 + q4]);
        unsigned a1 = __float_as_uint(Xs[r + 8][ks * 8 + q4]);
        unsigned a2 = __float_as_uint(Xs[r][ks * 8 + q4 + 4]);
        unsigned a3 = __float_as_uint(Xs[r + 8][ks * 8 + q4 + 4]);
#pragma unroll
        for (int nt = 0; nt < 8; nt++) {
            unsigned b0 = __float_as_uint(Ws2[nt * 8 + qn][ks * 8 + q4]);
            unsigned b1 = __float_as_uint(Ws2[nt * 8 + qn][ks * 8 + q4 + 4]);
            mma_tf32(acc[nt], a0, a1, a2, a3, b0, b1);
        }
    }

    if (which == 2) {
        // transpose through smem (bf16), then coalesced store of Vt rows
        __syncthreads();  // all mma reads of Xs/Ws2 done
        unsigned short* Ts = (unsigned short*)&Xs[0][0];  // [64 dims][72 keys] bf16
#pragma unroll
        for (int nt = 0; nt < 8; nt++) {
            int col = nt * 8 + 2 * q4;
            unsigned p0 = pack_bf16(acc[nt][0], acc[nt][1]);   // dims col, col+1 @ key r
            Ts[(col)     * 72 + r] = (unsigned short)(p0 & 0xffff);
            Ts[(col + 1) * 72 + r] = (unsigned short)(p0 >> 16);
            unsigned p1 = pack_bf16(acc[nt][2], acc[nt][3]);   // @ key r+8
            Ts[(col)     * 72 + r + 8] = (unsigned short)(p1 & 0xffff);
            Ts[(col + 1) * 72 + r + 8] = (unsigned short)(p1 >> 16);
        }
        __syncthreads();
        unsigned* vt = g_vt + ((size_t)(vn * NHD + vh) * HD) * (LSEQ / 2);
        const unsigned* Tsu = (const unsigned*)Ts;  // stride 36 u32 per dim row
#pragma unroll
        for (int i = 0; i < 16; i++) {
            int idx = t + i * 128;       // 0..2047 over 64 dims x 32 u32
            int d   = idx >> 5;
            int c   = idx & 31;
            vt[(size_t)d * (LSEQ / 2) + (vl0 >> 1) + c] = Tsu[d * 36 + c];
        }
    } else {
        unsigned short* outh = (which == 0) ? g_qh : g_kh;
#pragma unroll
        for (int nt = 0; nt < 8; nt++) {
            int col = nt * 8 + 2 * q4;
            float b0 = 0.f, b1 = 0.f;
            if (which == 0) { b0 = bq[col]; b1 = bq[col + 1]; }
            unsigned p0 = pack_bf16(acc[nt][0] + b0, acc[nt][1] + b1);
            *(unsigned*)(outh + (size_t)(rb + r) * 64 + col) = p0;
            unsigned p1 = pack_bf16(acc[nt][2] + b0, acc[nt][3] + b1);
            *(unsigned*)(outh + (size_t)(rb + r + 8) * 64 + col) = p1;
        }
    }
}

// ---------------- Kernel 2: flash attention (bf16 QK + bf16 PV, no shuffles) -
// grid (L/128, N*H), 256 threads = 8 warps x 16 q-rows. Double-buffered K/Vt/mask.
#define KH_STRIDE 36                 // u32 per K row (64 bf16 + pad)
#define KH_TILE  (64 * KH_STRIDE)
#define VT_STRIDE 36                 // u32 per Vt dim row (64 keys bf16 + pad)
#define VT_TILE  (64 * VT_STRIDE)
#define FLASH_SMEM_BYTES ((2 * KH_TILE + 2 * VT_TILE) * 4 + 2 * 64 * 4)

__global__ __launch_bounds__(256) void flash_kernel(const int* __restrict__ mask)
{
    extern __shared__ unsigned smu[];
    unsigned* KSu = smu;                          // [2][64][36] bf16x2 (K rows)
    unsigned* VTu = smu + 2 * KH_TILE;            // [2][64][36] bf16x2 (Vt: dim rows)
    int*      MS  = (int*)(smu + 2 * KH_TILE + 2 * VT_TILE);  // [2][64]

    const int t    = threadIdx.x;
    const int warp = t >> 5;
    const int lane = t & 31;
    const int qn   = lane >> 2;
    const int q4   = lane & 3;

    const int nh = blockIdx.y;
    const int n  = nh >> 4;
    const int h  = nh & 15;
    const int qbase = blockIdx.x * 128;

    const unsigned short* Qp = g_qh + (size_t)n * LSEQ * EMB + h * HD;
    const unsigned short* Kp = g_kh + (size_t)n * LSEQ * EMB + h * HD;
    const unsigned*       Vtp = g_vt + ((size_t)nh * HD) * (LSEQ / 2);
    const int* maskp = mask + n * LSEQ;

    auto load_tile = [&](int kt, int buf) {
        const int kb = kt * 64;
        // K: 64 key-rows x 128B
#pragma unroll
        for (int i = 0; i < 2; i++) {
            int idx = t + i * 256;
            int row = idx >> 3;
            int c   = idx & 7;
            cpa16(&KSu[buf * KH_TILE + row * KH_STRIDE + c * 4],
                  Kp + (size_t)(kb + row) * EMB + c * 8);
        }
        // Vt: 64 dim-rows x 128B (64 keys bf16)
#pragma unroll
        for (int i = 0; i < 2; i++) {
            int idx = t + i * 256;
            int row = idx >> 3;
            int c   = idx & 7;
            cpa16(&VTu[buf * VT_TILE + row * VT_STRIDE + c * 4],
                  Vtp + (size_t)row * (LSEQ / 2) + (kb >> 1) + c * 4);
        }
        if (t < 16) cpa16(&MS[buf * 64 + t * 4], maskp + kb + t * 4);
        cpa_commit();
    };

    load_tile(0, 0);

    // Q A-fragments (bf16, m16n8k16): direct global loads
    unsigned qa[4][4];
    const int qr = warp * 16 + qn;
#pragma unroll
    for (int ks = 0; ks < 4; ks++) {
        size_t base = (size_t)(qbase + qr) * EMB + ks * 16 + 2 * q4;
        qa[ks][0] = *(const unsigned*)(Qp + base);
        qa[ks][1] = *(const unsigned*)(Qp + base + (size_t)8 * EMB);
        qa[ks][2] = *(const unsigned*)(Qp + base + 8);
        qa[ks][3] = *(const unsigned*)(Qp + base + (size_t)8 * EMB + 8);
    }

    float o[8][4];
#pragma unroll
    for (int i = 0; i < 8; i++) { o[i][0] = o[i][1] = o[i][2] = o[i][3] = 0.f; }
    float mrow0 = -3.0e38f, mrow1 = -3.0e38f;
    float lrow0 = 0.f, lrow1 = 0.f;

    const float scl = 1.4426950408889634f / 32.0f;  // log2(e)/sqrt(E)

    for (int kt = 0; kt < LSEQ / 64; kt++) {
        const int buf = kt & 1;
        if (kt < LSEQ / 64 - 1) {
            load_tile(kt + 1, buf ^ 1);
            asm volatile("cp.async.wait_group 1;\n");
        } else {
            asm volatile("cp.async.wait_group 0;\n");
        }
        __syncthreads();

        const unsigned* Kb = KSu + buf * KH_TILE;
        const unsigned* Vb = VTu + buf * VT_TILE;
        const int*      Mb = MS + buf * 64;

        // S = Q @ K^T (bf16 k16)
        float s[8][4];
#pragma unroll
        for (int i = 0; i < 8; i++) { s[i][0] = s[i][1] = s[i][2] = s[i][3] = 0.f; }
#pragma unroll
        for (int ks = 0; ks < 4; ks++) {
#pragma unroll
            for (int nt = 0; nt < 8; nt++) {
                const unsigned* Krow = Kb + (nt * 8 + qn) * KH_STRIDE + ks * 8 + q4;
                mma_bf16(s[nt], qa[ks][0], qa[ks][1], qa[ks][2], qa[ks][3],
                         Krow[0], Krow[4]);
            }
        }

        // mask then scale (masked -> underflow ex2)
#pragma unroll
        for (int nt = 0; nt < 8; nt++) {
            int m0 = Mb[nt * 8 + 2 * q4];
            int m1 = Mb[nt * 8 + 2 * q4 + 1];
            s[nt][0] = m0 ? s[nt][0] * scl : -4.5e18f;
            s[nt][1] = m1 ? s[nt][1] * scl : -4.5e18f;
            s[nt][2] = m0 ? s[nt][2] * scl : -4.5e18f;
            s[nt][3] = m1 ? s[nt][3] * scl : -4.5e18f;
        }

        // online softmax (log2 domain), rows qn and qn+8
        float mx0 = s[0][0], mx1 = s[0][2];
#pragma unroll
        for (int nt = 0; nt < 8; nt++) {
            mx0 = fmaxf(mx0, fmaxf(s[nt][0], s[nt][1]));
            mx1 = fmaxf(mx1, fmaxf(s[nt][2], s[nt][3]));
        }
        mx0 = fmaxf(mx0, __shfl_xor_sync(0xffffffffu, mx0, 1));
        mx0 = fmaxf(mx0, __shfl_xor_sync(0xffffffffu, mx0, 2));
        mx1 = fmaxf(mx1, __shfl_xor_sync(0xffffffffu, mx1, 1));
        mx1 = fmaxf(mx1, __shfl_xor_sync(0xffffffffu, mx1, 2));

        float mn0 = fmaxf(mrow0, mx0);
        float mn1 = fmaxf(mrow1, mx1);
        float c0 = ex2(mrow0 - mn0);
        float c1 = ex2(mrow1 - mn1);
        mrow0 = mn0; mrow1 = mn1;

        float sum0 = 0.f, sum1 = 0.f;
#pragma unroll
        for (int nt = 0; nt < 8; nt++) {
            s[nt][0] = ex2(s[nt][0] - mn0); sum0 += s[nt][0];
            s[nt][1] = ex2(s[nt][1] - mn0); sum0 += s[nt][1];
            s[nt][2] = ex2(s[nt][2] - mn1); sum1 += s[nt][2];
            s[nt][3] = ex2(s[nt][3] - mn1); sum1 += s[nt][3];
        }
        sum0 += __shfl_xor_sync(0xffffffffu, sum0, 1);
        sum0 += __shfl_xor_sync(0xffffffffu, sum0, 2);
        sum1 += __shfl_xor_sync(0xffffffffu, sum1, 1);
        sum1 += __shfl_xor_sync(0xffffffffu, sum1, 2);
        lrow0 = lrow0 * c0 + sum0;
        lrow1 = lrow1 * c1 + sum1;

#pragma unroll
        for (int nt = 0; nt < 8; nt++) {
            o[nt][0] *= c0; o[nt][1] *= c0; o[nt][2] *= c1; o[nt][3] *= c1;
        }

        // O += P @ V (bf16 k16): C-frag -> A-frag by register packs, no shuffles
#pragma unroll
        for (int ks = 0; ks < 4; ks++) {
            unsigned a0 = pack_bf16(s[2 * ks][0],     s[2 * ks][1]);
            unsigned a1 = pack_bf16(s[2 * ks][2],     s[2 * ks][3]);
            unsigned a2 = pack_bf16(s[2 * ks + 1][0], s[2 * ks + 1][1]);
            unsigned a3 = pack_bf16(s[2 * ks + 1][2], s[2 * ks + 1][3]);
#pragma unroll
            for (int nt = 0; nt < 8; nt++) {
                const unsigned* Vrow = Vb + (nt * 8 + qn) * VT_STRIDE + ks * 8 + q4;
                mma_bf16(o[nt], a0, a1, a2, a3, Vrow[0], Vrow[4]);
            }
        }
        __syncthreads();
    }

    const float inv0 = 1.f / lrow0;
    const float inv1 = 1.f / lrow1;
    float* Op = g_ctx + (size_t)(n * LSEQ + qbase) * EMB + h * HD;
    const int row = warp * 16 + qn;
#pragma unroll
    for (int nt = 0; nt < 8; nt++) {
        int col = nt * 8 + 2 * q4;
        float2 v0;
        v0.x = __uint_as_float(f2tf(o[nt][0] * inv0));
        v0.y = __uint_as_float(f2tf(o[nt][1] * inv0));
        *(float2*)(Op + (size_t)row * EMB + col) = v0;
        float2 v1;
        v1.x = __uint_as_float(f2tf(o[nt][2] * inv1));
        v1.y = __uint_as_float(f2tf(o[nt][3] * inv1));
        *(float2*)(Op + (size_t)(row + 8) * EMB + col) = v1;
    }
}

// ---------------- Kernel 3: out = ctx @ Wo^T + bo (tf32 mma, K-step 32) ------
#define OG_AS_TILE (128 * 36)
#define OG_WS_TILE (64 * 36)
#define OG_SMEM_BYTES ((2 * OG_AS_TILE + 2 * OG_WS_TILE) * 4)

__global__ __launch_bounds__(256) void ogemm_kernel(
    const float* __restrict__ Wo, const float* __restrict__ bo, float* __restrict__ out)
{
    extern __shared__ float fsm[];
    float* AS = fsm;                    // [2][128][36]
    float* WS = fsm + 2 * OG_AS_TILE;   // [2][64][36]

    const int t    = threadIdx.x;
    const int warp = t >> 5;
    const int lane = t & 31;
    const int qn   = lane >> 2;
    const int q4   = lane & 3;
    const int mb   = blockIdx.y * 128;
    const int nb   = blockIdx.x * 64;

    auto load_tile = [&](int it, int buf) {
        const int kb = it * 32;
#pragma unroll
        for (int i = 0; i < 4; i++) {
            int idx = t + i * 256;
            int row = idx >> 3;
            int c   = idx & 7;
            cpa16(&AS[buf * OG_AS_TILE + row * 36 + c * 4],
                  g_ctx + (size_t)(mb + row) * 1024 + kb + c * 4);
        }
#pragma unroll
        for (int i = 0; i < 2; i++) {
            int idx = t + i * 256;
            int row = idx >> 3;
            int c   = idx & 7;
            cpa16(&WS[buf * OG_WS_TILE + row * 36 + c * 4],
                  Wo + (size_t)(nb + row) * 1024 + kb + c * 4);
        }
        cpa_commit();
    };

    load_tile(0, 0);

    float acc[8][4];
#pragma unroll
    for (int i = 0; i < 8; i++) { acc[i][0] = acc[i][1] = acc[i][2] = acc[i][3] = 0.f; }

    const int r = warp * 16 + qn;
    for (int it = 0; it < 32; it++) {
        const int buf = it & 1;
        if (it < 31) {
            load_tile(it + 1, buf ^ 1);
            asm volatile("cp.async.wait_group 1;\n");
        } else {
            asm volatile("cp.async.wait_group 0;\n");
        }
        __syncthreads();

        const float* Ab = AS + buf * OG_AS_TILE;
        const float* Wb = WS + buf * OG_WS_TILE;
#pragma unroll
        for (int ks = 0; ks < 4; ks++) {
            unsigned a0 = __float_as_uint(Ab[r * 36 + ks * 8 + q4]);
            unsigned a1 = __float_as_uint(Ab[(r + 8) * 36 + ks * 8 + q4]);
            unsigned a2 = __float_as_uint(Ab[r * 36 + ks * 8 + q4 + 4]);
            unsigned a3 = __float_as_uint(Ab[(r + 8) * 36 + ks * 8 + q4 + 4]);
#pragma unroll
            for (int nt = 0; nt < 8; nt++) {
                unsigned b0 = __float_as_uint(Wb[(nt * 8 + qn) * 36 + ks * 8 + q4]);
                unsigned b1 = __float_as_uint(Wb[(nt * 8 + qn) * 36 + ks * 8 + q4 + 4]);
                mma_tf32(acc[nt], a0, a1, a2, a3, b0, b1);
            }
        }
        __syncthreads();
    }

#pragma unroll
    for (int nt = 0; nt < 8; nt++) {
        int col = nt * 8 + 2 * q4;
        float b0 = bo[nb + col], b1 = bo[nb + col + 1];
        float2 v0; v0.x = acc[nt][0] + b0; v0.y = acc[nt][1] + b1;
        *(float2*)(out + (size_t)(mb + r) * 1024 + nb + col) = v0;
        float2 v1; v1.x = acc[nt][2] + b0; v1.y = acc[nt][3] + b1;
        *(float2*)(out + (size_t)(mb + r + 8) * 1024 + nb + col) = v1;
    }
}

extern "C" void kernel_launch(void* const* d_in, const int* in_sizes, int n_in,
                              void* d_out, int out_size) {
    const float* values = (const float*)d_in[0];
    const float* key    = (const float*)d_in[1];
    const float* query  = (const float*)d_in[2];
    const int*   mask   = (const int*)d_in[3];
    const float* Wv     = (const float*)d_in[4];
    const float* Wk     = (const float*)d_in[5];
    const float* Wq     = (const float*)d_in[6];
    const float* bq     = (const float*)d_in[7];
    const float* Wo     = (const float*)d_in[8];
    const float* bo     = (const float*)d_in[9];
    float* out = (float*)d_out;

    cudaFuncSetAttribute(flash_kernel, cudaFuncAttributeMaxDynamicSharedMemorySize,
                         FLASH_SMEM_BYTES);
    cudaFuncSetAttribute(ogemm_kernel, cudaFuncAttributeMaxDynamicSharedMemorySize,
                         OG_SMEM_BYTES);

    proj_kernel<<<dim3(NB * LSEQ * NHD / 64, 3), 128>>>(query, key, values, Wq, Wk, Wv, bq);
    flash_kernel<<<dim3(LSEQ / 128, NB * NHD), 256, FLASH_SMEM_BYTES>>>(mask);
    ogemm_kernel<<<dim3(EMB / 64, NB * LSEQ / 128), 256, OG_SMEM_BYTES>>>(Wo, bo, out);
}

// round 11
// speedup vs baseline: 2.5187x; 1.1635x over previous
#include <cuda_runtime.h>

#define NB   2
#define LSEQ 2048
#define EMB  1024
#define NHD  16
#define HD   64

__device__ unsigned short g_qh[NB * LSEQ * EMB];       // bf16 Q, (n,l,h,d)
__device__ unsigned short g_kh[NB * LSEQ * EMB];       // bf16 K, (n,l,h,d)
__device__ unsigned g_vt[NB * NHD * HD * (LSEQ / 2)];  // bf16x2 V^T: [(n*16+h)*64+d][l/2]
__device__ unsigned short g_ch[NB * LSEQ * EMB];       // bf16 ctx, (n,l,e)
__device__ unsigned short g_woh[EMB * EMB];            // bf16 Wo, row-major [n][k]

// returns {hi:16, lo:16} with lo in the low half
__device__ __forceinline__ unsigned pack_bf16(float lo, float hi) {
    unsigned r;
    asm("cvt.rn.bf16x2.f32 %0, %1, %2;" : "=r"(r) : "f"(hi), "f"(lo));
    return r;
}

__device__ __forceinline__ float ex2(float x) {
    float r;
    asm("ex2.approx.ftz.f32 %0, %1;" : "=f"(r) : "f"(x));
    return r;
}

__device__ __forceinline__ void mma_tf32(float* d,
                                         unsigned a0, unsigned a1, unsigned a2, unsigned a3,
                                         unsigned b0, unsigned b1) {
    asm("mma.sync.aligned.m16n8k8.row.col.f32.tf32.tf32.f32 "
        "{%0,%1,%2,%3}, {%4,%5,%6,%7}, {%8,%9}, {%0,%1,%2,%3};\n"
        : "+f"(d[0]), "+f"(d[1]), "+f"(d[2]), "+f"(d[3])
        : "r"(a0), "r"(a1), "r"(a2), "r"(a3), "r"(b0), "r"(b1));
}

__device__ __forceinline__ void mma_bf16(float* d,
                                         unsigned a0, unsigned a1, unsigned a2, unsigned a3,
                                         unsigned b0, unsigned b1) {
    asm("mma.sync.aligned.m16n8k16.row.col.f32.bf16.bf16.f32 "
        "{%0,%1,%2,%3}, {%4,%5,%6,%7}, {%8,%9}, {%0,%1,%2,%3};\n"
        : "+f"(d[0]), "+f"(d[1]), "+f"(d[2]), "+f"(d[3])
        : "r"(a0), "r"(a1), "r"(a2), "r"(a3), "r"(b0), "r"(b1));
}

__device__ __forceinline__ void cpa16(void* s, const void* g) {
    unsigned sa = (unsigned)__cvta_generic_to_shared(s);
    asm volatile("cp.async.cg.shared.global [%0], [%1], 16;\n"
                 :: "r"(sa), "l"(__cvta_generic_to_global(g)));
}
__device__ __forceinline__ void cpa_commit() { asm volatile("cp.async.commit_group;\n"); }

// ---------------- Kernel 0: Wo fp32 -> bf16 ----------------
__global__ __launch_bounds__(256) void wconv_kernel(const float* __restrict__ Wo)
{
    int i = (blockIdx.x * 256 + threadIdx.x) * 4;   // 4 floats per thread
    float4 w = *(const float4*)(Wo + i);
    uint2 p;
    p.x = pack_bf16(w.x, w.y);
    p.y = pack_bf16(w.z, w.w);
    *(uint2*)(g_woh + i) = p;
}

// ---------------- Kernel 1: per-head projections via tf32 mma ----------------
// which 0: Q -> bf16 row-major. 1: K -> bf16 row-major.
// 2: V -> bf16 TRANSPOSED g_vt[(n*16+h)*64+d][l] (per-(n,h) l-tiles of 64).
__global__ __launch_bounds__(128) void proj_kernel(
    const float* __restrict__ xq, const float* __restrict__ xk, const float* __restrict__ xv,
    const float* __restrict__ Wq, const float* __restrict__ Wk, const float* __restrict__ Wv,
    const float* __restrict__ bq)
{
    __shared__ float Xs[64][68];
    __shared__ float Ws2[64][68];

    const int which = blockIdx.y;
    const float* x = (which == 0) ? xq : (which == 1) ? xk : xv;
    const float* W = (which == 0) ? Wq : (which == 1) ? Wk : Wv;

    const int t    = threadIdx.x;
    const int warp = t >> 5;
    const int lane = t & 31;
    const int qn   = lane >> 2;
    const int q4   = lane & 3;

    int vn = 0, vh = 0, vl0 = 0;
    if (which == 2) {
        int b = blockIdx.x;
        vn  = b / (NHD * (LSEQ / 64));
        int rem = b % (NHD * (LSEQ / 64));
        vh  = rem / (LSEQ / 64);
        vl0 = (rem % (LSEQ / 64)) * 64;
    }
    const int rb = blockIdx.x * 64;

#pragma unroll
    for (int i = 0; i < 8; i++) {
        int f4  = t + i * 128;
        int row = f4 >> 4;
        int d0  = (f4 & 15) << 2;
        if (which == 2) {
            *(float4*)&Xs[row][d0] =
                *(const float4*)(x + ((size_t)(vn * LSEQ + vl0 + row)) * EMB + vh * HD + d0);
        } else {
            *(float4*)&Xs[row][d0] = *(const float4*)(x + (size_t)(rb + row) * 64 + d0);
        }
        *(float4*)&Ws2[row][d0] = *(const float4*)(W + row * 64 + d0);
    }
    __syncthreads();

    float acc[8][4];
#pragma unroll
    for (int i = 0; i < 8; i++) { acc[i][0] = acc[i][1] = acc[i][2] = acc[i][3] = 0.f; }

    const int r = warp * 16 + qn;
#pragma unroll
    for (int ks = 0; ks < 8; ks++) {
        unsigned a0 = __float_as_uint(Xs[r][ks * 8 + q4]);
        unsigned a1 = __float_as_uint(Xs[r + 8][ks * 8 + q4]);
        unsigned a2 = __float_as_uint(Xs[r][ks * 8 + q4 + 4]);
        unsigned a3 = __float_as_uint(Xs[r + 8][ks * 8 + q4 + 4]);
#pragma unroll
        for (int nt = 0; nt < 8; nt++) {
            unsigned b0 = __float_as_uint(Ws2[nt * 8 + qn][ks * 8 + q4]);
            unsigned b1 = __float_as_uint(Ws2[nt * 8 + qn][ks * 8 + q4 + 4]);
            mma_tf32(acc[nt], a0, a1, a2, a3, b0, b1);
        }
    }

    if (which == 2) {
        __syncthreads();
        unsigned short* Ts = (unsigned short*)&Xs[0][0];  // [64 dims][72 keys] bf16
#pragma unroll
        for (int nt = 0; nt < 8; nt++) {
            int col = nt * 8 + 2 * q4;
            unsigned p0 = pack_bf16(acc[nt][0], acc[nt][1]);
            Ts[(col)     * 72 + r] = (unsigned short)(p0 & 0xffff);
            Ts[(col + 1) * 72 + r] = (unsigned short)(p0 >> 16);
            unsigned p1 = pack_bf16(acc[nt][2], acc[nt][3]);
            Ts[(col)     * 72 + r + 8] = (unsigned short)(p1 & 0xffff);
            Ts[(col + 1) * 72 + r + 8] = (unsigned short)(p1 >> 16);
        }
        __syncthreads();
        unsigned* vt = g_vt + ((size_t)(vn * NHD + vh) * HD) * (LSEQ / 2);
        const unsigned* Tsu = (const unsigned*)Ts;
#pragma unroll
        for (int i = 0; i < 16; i++) {
            int idx = t + i * 128;
            int d   = idx >> 5;
            int c   = idx & 31;
            vt[(size_t)d * (LSEQ / 2) + (vl0 >> 1) + c] = Tsu[d * 36 + c];
        }
    } else {
        unsigned short* outh = (which == 0) ? g_qh : g_kh;
#pragma unroll
        for (int nt = 0; nt < 8; nt++) {
            int col = nt * 8 + 2 * q4;
            float b0 = 0.f, b1 = 0.f;
            if (which == 0) { b0 = bq[col]; b1 = bq[col + 1]; }
            unsigned p0 = pack_bf16(acc[nt][0] + b0, acc[nt][1] + b1);
            *(unsigned*)(outh + (size_t)(rb + r) * 64 + col) = p0;
            unsigned p1 = pack_bf16(acc[nt][2] + b0, acc[nt][3] + b1);
            *(unsigned*)(outh + (size_t)(rb + r + 8) * 64 + col) = p1;
        }
    }
}

// ---------------- Kernel 2: flash attention (bf16 QK + bf16 PV) --------------
#define KH_STRIDE 36
#define KH_TILE  (64 * KH_STRIDE)
#define VT_STRIDE 36
#define VT_TILE  (64 * VT_STRIDE)
#define FLASH_SMEM_BYTES ((2 * KH_TILE + 2 * VT_TILE) * 4 + 2 * 64 * 4)

__global__ __launch_bounds__(256) void flash_kernel(const int* __restrict__ mask)
{
    extern __shared__ unsigned smu[];
    unsigned* KSu = smu;                          // [2][64][36] bf16x2 (K rows)
    unsigned* VTu = smu + 2 * KH_TILE;            // [2][64][36] bf16x2 (Vt dim rows)
    int*      MS  = (int*)(smu + 2 * KH_TILE + 2 * VT_TILE);  // [2][64]

    const int t    = threadIdx.x;
    const int warp = t >> 5;
    const int lane = t & 31;
    const int qn   = lane >> 2;
    const int q4   = lane & 3;

    const int nh = blockIdx.y;
    const int n  = nh >> 4;
    const int h  = nh & 15;
    const int qbase = blockIdx.x * 128;

    const unsigned short* Qp = g_qh + (size_t)n * LSEQ * EMB + h * HD;
    const unsigned short* Kp = g_kh + (size_t)n * LSEQ * EMB + h * HD;
    const unsigned*       Vtp = g_vt + ((size_t)nh * HD) * (LSEQ / 2);
    const int* maskp = mask + n * LSEQ;

    auto load_tile = [&](int kt, int buf) {
        const int kb = kt * 64;
#pragma unroll
        for (int i = 0; i < 2; i++) {
            int idx = t + i * 256;
            int row = idx >> 3;
            int c   = idx & 7;
            cpa16(&KSu[buf * KH_TILE + row * KH_STRIDE + c * 4],
                  Kp + (size_t)(kb + row) * EMB + c * 8);
        }
#pragma unroll
        for (int i = 0; i < 2; i++) {
            int idx = t + i * 256;
            int row = idx >> 3;
            int c   = idx & 7;
            cpa16(&VTu[buf * VT_TILE + row * VT_STRIDE + c * 4],
                  Vtp + (size_t)row * (LSEQ / 2) + (kb >> 1) + c * 4);
        }
        if (t < 16) cpa16(&MS[buf * 64 + t * 4], maskp + kb + t * 4);
        cpa_commit();
    };

    load_tile(0, 0);

    unsigned qa[4][4];
    const int qr = warp * 16 + qn;
#pragma unroll
    for (int ks = 0; ks < 4; ks++) {
        size_t base = (size_t)(qbase + qr) * EMB + ks * 16 + 2 * q4;
        qa[ks][0] = *(const unsigned*)(Qp + base);
        qa[ks][1] = *(const unsigned*)(Qp + base + (size_t)8 * EMB);
        qa[ks][2] = *(const unsigned*)(Qp + base + 8);
        qa[ks][3] = *(const unsigned*)(Qp + base + (size_t)8 * EMB + 8);
    }

    float o[8][4];
#pragma unroll
    for (int i = 0; i < 8; i++) { o[i][0] = o[i][1] = o[i][2] = o[i][3] = 0.f; }
    float mrow0 = -3.0e38f, mrow1 = -3.0e38f;
    float lrow0 = 0.f, lrow1 = 0.f;

    const float scl = 1.4426950408889634f / 32.0f;  // log2(e)/sqrt(E)

    for (int kt = 0; kt < LSEQ / 64; kt++) {
        const int buf = kt & 1;
        if (kt < LSEQ / 64 - 1) {
            load_tile(kt + 1, buf ^ 1);
            asm volatile("cp.async.wait_group 1;\n");
        } else {
            asm volatile("cp.async.wait_group 0;\n");
        }
        __syncthreads();

        const unsigned* Kb = KSu + buf * KH_TILE;
        const unsigned* Vb = VTu + buf * VT_TILE;
        const int*      Mb = MS + buf * 64;

        float s[8][4];
#pragma unroll
        for (int i = 0; i < 8; i++) { s[i][0] = s[i][1] = s[i][2] = s[i][3] = 0.f; }
#pragma unroll
        for (int ks = 0; ks < 4; ks++) {
#pragma unroll
            for (int nt = 0; nt < 8; nt++) {
                const unsigned* Krow = Kb + (nt * 8 + qn) * KH_STRIDE + ks * 8 + q4;
                mma_bf16(s[nt], qa[ks][0], qa[ks][1], qa[ks][2], qa[ks][3],
                         Krow[0], Krow[4]);
            }
        }

#pragma unroll
        for (int nt = 0; nt < 8; nt++) {
            int m0 = Mb[nt * 8 + 2 * q4];
            int m1 = Mb[nt * 8 + 2 * q4 + 1];
            s[nt][0] = m0 ? s[nt][0] * scl : -4.5e18f;
            s[nt][1] = m1 ? s[nt][1] * scl : -4.5e18f;
            s[nt][2] = m0 ? s[nt][2] * scl : -4.5e18f;
            s[nt][3] = m1 ? s[nt][3] * scl : -4.5e18f;
        }

        float mx0 = s[0][0], mx1 = s[0][2];
#pragma unroll
        for (int nt = 0; nt < 8; nt++) {
            mx0 = fmaxf(mx0, fmaxf(s[nt][0], s[nt][1]));
            mx1 = fmaxf(mx1, fmaxf(s[nt][2], s[nt][3]));
        }
        mx0 = fmaxf(mx0, __shfl_xor_sync(0xffffffffu, mx0, 1));
        mx0 = fmaxf(mx0, __shfl_xor_sync(0xffffffffu, mx0, 2));
        mx1 = fmaxf(mx1, __shfl_xor_sync(0xffffffffu, mx1, 1));
        mx1 = fmaxf(mx1, __shfl_xor_sync(0xffffffffu, mx1, 2));

        float mn0 = fmaxf(mrow0, mx0);
        float mn1 = fmaxf(mrow1, mx1);
        float c0 = ex2(mrow0 - mn0);
        float c1 = ex2(mrow1 - mn1);
        mrow0 = mn0; mrow1 = mn1;

        float sum0 = 0.f, sum1 = 0.f;
#pragma unroll
        for (int nt = 0; nt < 8; nt++) {
            s[nt][0] = ex2(s[nt][0] - mn0); sum0 += s[nt][0];
            s[nt][1] = ex2(s[nt][1] - mn0); sum0 += s[nt][1];
            s[nt][2] = ex2(s[nt][2] - mn1); sum1 += s[nt][2];
            s[nt][3] = ex2(s[nt][3] - mn1); sum1 += s[nt][3];
        }
        sum0 += __shfl_xor_sync(0xffffffffu, sum0, 1);
        sum0 += __shfl_xor_sync(0xffffffffu, sum0, 2);
        sum1 += __shfl_xor_sync(0xffffffffu, sum1, 1);
        sum1 += __shfl_xor_sync(0xffffffffu, sum1, 2);
        lrow0 = lrow0 * c0 + sum0;
        lrow1 = lrow1 * c1 + sum1;

#pragma unroll
        for (int nt = 0; nt < 8; nt++) {
            o[nt][0] *= c0; o[nt][1] *= c0; o[nt][2] *= c1; o[nt][3] *= c1;
        }

        // O += P @ V (bf16 k16): C-frag -> A-frag by register packs
#pragma unroll
        for (int ks = 0; ks < 4; ks++) {
            unsigned a0 = pack_bf16(s[2 * ks][0],     s[2 * ks][1]);
            unsigned a1 = pack_bf16(s[2 * ks][2],     s[2 * ks][3]);
            unsigned a2 = pack_bf16(s[2 * ks + 1][0], s[2 * ks + 1][1]);
            unsigned a3 = pack_bf16(s[2 * ks + 1][2], s[2 * ks + 1][3]);
#pragma unroll
            for (int nt = 0; nt < 8; nt++) {
                const unsigned* Vrow = Vb + (nt * 8 + qn) * VT_STRIDE + ks * 8 + q4;
                mma_bf16(o[nt], a0, a1, a2, a3, Vrow[0], Vrow[4]);
            }
        }
        __syncthreads();
    }

    const float inv0 = 1.f / lrow0;
    const float inv1 = 1.f / lrow1;
    unsigned short* Op = g_ch + (size_t)(n * LSEQ + qbase) * EMB + h * HD;
    const int row = warp * 16 + qn;
#pragma unroll
    for (int nt = 0; nt < 8; nt++) {
        int col = nt * 8 + 2 * q4;
        *(unsigned*)(Op + (size_t)row * EMB + col) =
            pack_bf16(o[nt][0] * inv0, o[nt][1] * inv0);
        *(unsigned*)(Op + (size_t)(row + 8) * EMB + col) =
            pack_bf16(o[nt][2] * inv1, o[nt][3] * inv1);
    }
}

// ---------------- Kernel 3: out = ctx @ Wo^T + bo (bf16 mma, K-step 64) ------
#define OG_AS_TILE (128 * 36)   // u32 per A stage
#define OG_WS_TILE (64 * 36)    // u32 per W stage
#define OG_SMEM_BYTES ((2 * OG_AS_TILE + 2 * OG_WS_TILE) * 4)

__global__ __launch_bounds__(256) void ogemm_kernel(
    const float* __restrict__ bo, float* __restrict__ out)
{
    extern __shared__ unsigned usm[];
    unsigned* AS = usm;                    // [2][128][36] bf16x2
    unsigned* WS = usm + 2 * OG_AS_TILE;   // [2][64][36] bf16x2

    const int t    = threadIdx.x;
    const int warp = t >> 5;
    const int lane = t & 31;
    const int qn   = lane >> 2;
    const int q4   = lane & 3;
    const int mb   = blockIdx.y * 128;
    const int nb   = blockIdx.x * 64;

    auto load_tile = [&](int it, int buf) {
        const int kb = it * 64;
        // A: 128 rows x 64 bf16 = 128 rows x 8 chunks(16B)
#pragma unroll
        for (int i = 0; i < 4; i++) {
            int idx = t + i * 256;
            int row = idx >> 3;
            int c   = idx & 7;
            cpa16(&AS[buf * OG_AS_TILE + row * 36 + c * 4],
                  g_ch + (size_t)(mb + row) * 1024 + kb + c * 8);
        }
        // W: 64 rows x 8 chunks
#pragma unroll
        for (int i = 0; i < 2; i++) {
            int idx = t + i * 256;
            int row = idx >> 3;
            int c   = idx & 7;
            cpa16(&WS[buf * OG_WS_TILE + row * 36 + c * 4],
                  g_woh + (size_t)(nb + row) * 1024 + kb + c * 8);
        }
        cpa_commit();
    };

    load_tile(0, 0);

    float acc[8][4];
#pragma unroll
    for (int i = 0; i < 8; i++) { acc[i][0] = acc[i][1] = acc[i][2] = acc[i][3] = 0.f; }

    const int r = warp * 16 + qn;
    for (int it = 0; it < 16; it++) {
        const int buf = it & 1;
        if (it < 15) {
            load_tile(it + 1, buf ^ 1);
            asm volatile("cp.async.wait_group 1;\n");
        } else {
            asm volatile("cp.async.wait_group 0;\n");
        }
        __syncthreads();

        const unsigned* Ab = AS + buf * OG_AS_TILE;
        const unsigned* Wb = WS + buf * OG_WS_TILE;
#pragma unroll
        for (int ks = 0; ks < 4; ks++) {
            unsigned a0 = Ab[r * 36 + ks * 8 + q4];
            unsigned a1 = Ab[(r + 8) * 36 + ks * 8 + q4];
            unsigned a2 = Ab[r * 36 + ks * 8 + q4 + 4];
            unsigned a3 = Ab[(r + 8) * 36 + ks * 8 + q4 + 4];
#pragma unroll
            for (int nt = 0; nt < 8; nt++) {
                const unsigned* Wrow = Wb + (nt * 8 + qn) * 36 + ks * 8 + q4;
                mma_bf16(acc[nt], a0, a1, a2, a3, Wrow[0], Wrow[4]);
            }
        }
        __syncthreads();
    }

#pragma unroll
    for (int nt = 0; nt < 8; nt++) {
        int col = nt * 8 + 2 * q4;
        float b0 = bo[nb + col], b1 = bo[nb + col + 1];
        float2 v0; v0.x = acc[nt][0] + b0; v0.y = acc[nt][1] + b1;
        *(float2*)(out + (size_t)(mb + r) * 1024 + nb + col) = v0;
        float2 v1; v1.x = acc[nt][2] + b0; v1.y = acc[nt][3] + b1;
        *(float2*)(out + (size_t)(mb + r + 8) * 1024 + nb + col) = v1;
    }
}

extern "C" void kernel_launch(void* const* d_in, const int* in_sizes, int n_in,
                              void* d_out, int out_size) {
    const float* values = (const float*)d_in[0];
    const float* key    = (const float*)d_in[1];
    const float* query  = (const float*)d_in[2];
    const int*   mask   = (const int*)d_in[3];
    const float* Wv     = (const float*)d_in[4];
    const float* Wk     = (const float*)d_in[5];
    const float* Wq     = (const float*)d_in[6];
    const float* bq     = (const float*)d_in[7];
    const float* Wo     = (const float*)d_in[8];
    const float* bo     = (const float*)d_in[9];
    float* out = (float*)d_out;

    cudaFuncSetAttribute(flash_kernel, cudaFuncAttributeMaxDynamicSharedMemorySize,
                         FLASH_SMEM_BYTES);
    cudaFuncSetAttribute(ogemm_kernel, cudaFuncAttributeMaxDynamicSharedMemorySize,
                         OG_SMEM_BYTES);

    wconv_kernel<<<EMB * EMB / (256 * 4), 256>>>(Wo);
    proj_kernel<<<dim3(NB * LSEQ * NHD / 64, 3), 128>>>(query, key, values, Wq, Wk, Wv, bq);
    flash_kernel<<<dim3(LSEQ / 128, NB * NHD), 256, FLASH_SMEM_BYTES>>>(mask);
    ogemm_kernel<<<dim3(EMB / 64, NB * LSEQ / 128), 256, OG_SMEM_BYTES>>>(bo, out);
}

// round 12
// speedup vs baseline: 2.6755x; 1.0623x over previous
#include <cuda_runtime.h>

#define NB   2
#define LSEQ 2048
#define EMB  1024
#define NHD  16
#define HD   64

__device__ unsigned short g_qh[NB * LSEQ * EMB];       // bf16 Q, (n,l,h,d)
__device__ unsigned short g_kh[NB * LSEQ * EMB];       // bf16 K, (n,l,h,d)
__device__ unsigned g_vt[NB * NHD * HD * (LSEQ / 2)];  // bf16x2 V^T: [(n*16+h)*64+d][l/2]
__device__ unsigned short g_ch[NB * LSEQ * EMB];       // bf16 ctx, (n,l,e)
__device__ unsigned short g_woh[EMB * EMB];            // bf16 Wo, row-major [n][k]

// returns {hi:16, lo:16} with lo in the low half
__device__ __forceinline__ unsigned pack_bf16(float lo, float hi) {
    unsigned r;
    asm("cvt.rn.bf16x2.f32 %0, %1, %2;" : "=r"(r) : "f"(hi), "f"(lo));
    return r;
}

__device__ __forceinline__ float ex2(float x) {
    float r;
    asm("ex2.approx.ftz.f32 %0, %1;" : "=f"(r) : "f"(x));
    return r;
}

__device__ __forceinline__ void mma_tf32(float* d,
                                         unsigned a0, unsigned a1, unsigned a2, unsigned a3,
                                         unsigned b0, unsigned b1) {
    asm("mma.sync.aligned.m16n8k8.row.col.f32.tf32.tf32.f32 "
        "{%0,%1,%2,%3}, {%4,%5,%6,%7}, {%8,%9}, {%0,%1,%2,%3};\n"
        : "+f"(d[0]), "+f"(d[1]), "+f"(d[2]), "+f"(d[3])
        : "r"(a0), "r"(a1), "r"(a2), "r"(a3), "r"(b0), "r"(b1));
}

__device__ __forceinline__ void mma_bf16(float* d,
                                         unsigned a0, unsigned a1, unsigned a2, unsigned a3,
                                         unsigned b0, unsigned b1) {
    asm("mma.sync.aligned.m16n8k16.row.col.f32.bf16.bf16.f32 "
        "{%0,%1,%2,%3}, {%4,%5,%6,%7}, {%8,%9}, {%0,%1,%2,%3};\n"
        : "+f"(d[0]), "+f"(d[1]), "+f"(d[2]), "+f"(d[3])
        : "r"(a0), "r"(a1), "r"(a2), "r"(a3), "r"(b0), "r"(b1));
}

__device__ __forceinline__ void ldsm4(unsigned& r0, unsigned& r1, unsigned& r2, unsigned& r3,
                                      unsigned saddr) {
    asm volatile("ldmatrix.sync.aligned.m8n8.x4.shared.b16 {%0,%1,%2,%3}, [%4];"
                 : "=r"(r0), "=r"(r1), "=r"(r2), "=r"(r3) : "r"(saddr));
}

__device__ __forceinline__ void cpa16(void* s, const void* g) {
    unsigned sa = (unsigned)__cvta_generic_to_shared(s);
    asm volatile("cp.async.cg.shared.global [%0], [%1], 16;\n"
                 :: "r"(sa), "l"(__cvta_generic_to_global(g)));
}
__device__ __forceinline__ void cpa_commit() { asm volatile("cp.async.commit_group;\n"); }

// ---------------- Kernel 0: Wo fp32 -> bf16 ----------------
__global__ __launch_bounds__(256) void wconv_kernel(const float* __restrict__ Wo)
{
    int i = (blockIdx.x * 256 + threadIdx.x) * 4;
    float4 w = *(const float4*)(Wo + i);
    uint2 p;
    p.x = pack_bf16(w.x, w.y);
    p.y = pack_bf16(w.z, w.w);
    *(uint2*)(g_woh + i) = p;
}

// ---------------- Kernel 1: per-head projections via tf32 mma ----------------
__global__ __launch_bounds__(128) void proj_kernel(
    const float* __restrict__ xq, const float* __restrict__ xk, const float* __restrict__ xv,
    const float* __restrict__ Wq, const float* __restrict__ Wk, const float* __restrict__ Wv,
    const float* __restrict__ bq)
{
    __shared__ float Xs[64][68];
    __shared__ float Ws2[64][68];

    const int which = blockIdx.y;
    const float* x = (which == 0) ? xq : (which == 1) ? xk : xv;
    const float* W = (which == 0) ? Wq : (which == 1) ? Wk : Wv;

    const int t    = threadIdx.x;
    const int warp = t >> 5;
    const int lane = t & 31;
    const int qn   = lane >> 2;
    const int q4   = lane & 3;

    int vn = 0, vh = 0, vl0 = 0;
    if (which == 2) {
        int b = blockIdx.x;
        vn  = b / (NHD * (LSEQ / 64));
        int rem = b % (NHD * (LSEQ / 64));
        vh  = rem / (LSEQ / 64);
        vl0 = (rem % (LSEQ / 64)) * 64;
    }
    const int rb = blockIdx.x * 64;

#pragma unroll
    for (int i = 0; i < 8; i++) {
        int f4  = t + i * 128;
        int row = f4 >> 4;
        int d0  = (f4 & 15) << 2;
        if (which == 2) {
            *(float4*)&Xs[row][d0] =
                *(const float4*)(x + ((size_t)(vn * LSEQ + vl0 + row)) * EMB + vh * HD + d0);
        } else {
            *(float4*)&Xs[row][d0] = *(const float4*)(x + (size_t)(rb + row) * 64 + d0);
        }
        *(float4*)&Ws2[row][d0] = *(const float4*)(W + row * 64 + d0);
    }
    __syncthreads();

    float acc[8][4];
#pragma unroll
    for (int i = 0; i < 8; i++) { acc[i][0] = acc[i][1] = acc[i][2] = acc[i][3] = 0.f; }

    const int r = warp * 16 + qn;
#pragma unroll
    for (int ks = 0; ks < 8; ks++) {
        unsigned a0 = __float_as_uint(Xs[r][ks * 8 + q4]);
        unsigned a1 = __float_as_uint(Xs[r + 8][ks * 8 + q4]);
        unsigned a2 = __float_as_uint(Xs[r][ks * 8 + q4 + 4]);
        unsigned a3 = __float_as_uint(Xs[r + 8][ks * 8 + q4 + 4]);
#pragma unroll
        for (int nt = 0; nt < 8; nt++) {
            unsigned b0 = __float_as_uint(Ws2[nt * 8 + qn][ks * 8 + q4]);
            unsigned b1 = __float_as_uint(Ws2[nt * 8 + qn][ks * 8 + q4 + 4]);
            mma_tf32(acc[nt], a0, a1, a2, a3, b0, b1);
        }
    }

    if (which == 2) {
        __syncthreads();
        unsigned short* Ts = (unsigned short*)&Xs[0][0];  // [64 dims][72 keys] bf16
#pragma unroll
        for (int nt = 0; nt < 8; nt++) {
            int col = nt * 8 + 2 * q4;
            unsigned p0 = pack_bf16(acc[nt][0], acc[nt][1]);
            Ts[(col)     * 72 + r] = (unsigned short)(p0 & 0xffff);
            Ts[(col + 1) * 72 + r] = (unsigned short)(p0 >> 16);
            unsigned p1 = pack_bf16(acc[nt][2], acc[nt][3]);
            Ts[(col)     * 72 + r + 8] = (unsigned short)(p1 & 0xffff);
            Ts[(col + 1) * 72 + r + 8] = (unsigned short)(p1 >> 16);
        }
        __syncthreads();
        unsigned* vt = g_vt + ((size_t)(vn * NHD + vh) * HD) * (LSEQ / 2);
        const unsigned* Tsu = (const unsigned*)Ts;
#pragma unroll
        for (int i = 0; i < 16; i++) {
            int idx = t + i * 128;
            int d   = idx >> 5;
            int c   = idx & 31;
            vt[(size_t)d * (LSEQ / 2) + (vl0 >> 1) + c] = Tsu[d * 36 + c];
        }
    } else {
        unsigned short* outh = (which == 0) ? g_qh : g_kh;
#pragma unroll
        for (int nt = 0; nt < 8; nt++) {
            int col = nt * 8 + 2 * q4;
            float b0 = 0.f, b1 = 0.f;
            if (which == 0) { b0 = bq[col]; b1 = bq[col + 1]; }
            unsigned p0 = pack_bf16(acc[nt][0] + b0, acc[nt][1] + b1);
            *(unsigned*)(outh + (size_t)(rb + r) * 64 + col) = p0;
            unsigned p1 = pack_bf16(acc[nt][2] + b0, acc[nt][3] + b1);
            *(unsigned*)(outh + (size_t)(rb + r + 8) * 64 + col) = p1;
        }
    }
}

// ---------------- Kernel 2: flash attention (bf16, ldmatrix frags) ----------
#define KH_STRIDE 36
#define KH_TILE  (64 * KH_STRIDE)
#define VT_STRIDE 36
#define VT_TILE  (64 * VT_STRIDE)
#define FLASH_SMEM_BYTES ((2 * KH_TILE + 2 * VT_TILE) * 4 + 2 * 64 * 4)

__global__ __launch_bounds__(256) void flash_kernel(const int* __restrict__ mask)
{
    extern __shared__ unsigned smu[];
    unsigned* KSu = smu;                          // [2][64][36] bf16x2 (K key-rows)
    unsigned* VTu = smu + 2 * KH_TILE;            // [2][64][36] bf16x2 (Vt dim-rows)
    int*      MS  = (int*)(smu + 2 * KH_TILE + 2 * VT_TILE);  // [2][64]

    const int t    = threadIdx.x;
    const int warp = t >> 5;
    const int lane = t & 31;
    const int qn   = lane >> 2;
    const int q4   = lane & 3;

    // ldmatrix B-operand addressing: matrix id m = lane>>3
    const int rowp = ((lane >> 4) & 1) * 8 + (lane & 7);  // row within 16-row pair
    const int ksel = ((lane >> 3) & 1) * 4;               // u32 offset for k+8 half

    const int nh = blockIdx.y;
    const int n  = nh >> 4;
    const int h  = nh & 15;
    const int qbase = blockIdx.x * 128;

    const unsigned short* Qp = g_qh + (size_t)n * LSEQ * EMB + h * HD;
    const unsigned short* Kp = g_kh + (size_t)n * LSEQ * EMB + h * HD;
    const unsigned*       Vtp = g_vt + ((size_t)nh * HD) * (LSEQ / 2);
    const int* maskp = mask + n * LSEQ;

    const unsigned ksm_base = (unsigned)__cvta_generic_to_shared(KSu);
    const unsigned vsm_base = (unsigned)__cvta_generic_to_shared(VTu);

    auto load_tile = [&](int kt, int buf) {
        const int kb = kt * 64;
#pragma unroll
        for (int i = 0; i < 2; i++) {
            int idx = t + i * 256;
            int row = idx >> 3;
            int c   = idx & 7;
            cpa16(&KSu[buf * KH_TILE + row * KH_STRIDE + c * 4],
                  Kp + (size_t)(kb + row) * EMB + c * 8);
        }
#pragma unroll
        for (int i = 0; i < 2; i++) {
            int idx = t + i * 256;
            int row = idx >> 3;
            int c   = idx & 7;
            cpa16(&VTu[buf * VT_TILE + row * VT_STRIDE + c * 4],
                  Vtp + (size_t)row * (LSEQ / 2) + (kb >> 1) + c * 4);
        }
        if (t < 16) cpa16(&MS[buf * 64 + t * 4], maskp + kb + t * 4);
        cpa_commit();
    };

    load_tile(0, 0);

    unsigned qa[4][4];
    const int qr = warp * 16 + qn;
#pragma unroll
    for (int ks = 0; ks < 4; ks++) {
        size_t base = (size_t)(qbase + qr) * EMB + ks * 16 + 2 * q4;
        qa[ks][0] = *(const unsigned*)(Qp + base);
        qa[ks][1] = *(const unsigned*)(Qp + base + (size_t)8 * EMB);
        qa[ks][2] = *(const unsigned*)(Qp + base + 8);
        qa[ks][3] = *(const unsigned*)(Qp + base + (size_t)8 * EMB + 8);
    }

    float o[8][4];
#pragma unroll
    for (int i = 0; i < 8; i++) { o[i][0] = o[i][1] = o[i][2] = o[i][3] = 0.f; }
    float mrow0 = -3.0e38f, mrow1 = -3.0e38f;
    float lrow0 = 0.f, lrow1 = 0.f;

    const float scl = 1.4426950408889634f / 32.0f;  // log2(e)/sqrt(E)

    for (int kt = 0; kt < LSEQ / 64; kt++) {
        const int buf = kt & 1;
        if (kt < LSEQ / 64 - 1) {
            load_tile(kt + 1, buf ^ 1);
            asm volatile("cp.async.wait_group 1;\n");
        } else {
            asm volatile("cp.async.wait_group 0;\n");
        }
        __syncthreads();

        const unsigned kbuf_s = ksm_base + (unsigned)(buf * KH_TILE) * 4u;
        const unsigned vbuf_s = vsm_base + (unsigned)(buf * VT_TILE) * 4u;
        const int*     Mb     = MS + buf * 64;

        // S = Q @ K^T (bf16 k16), K frags via ldmatrix.x4
        float s[8][4];
#pragma unroll
        for (int i = 0; i < 8; i++) { s[i][0] = s[i][1] = s[i][2] = s[i][3] = 0.f; }
#pragma unroll
        for (int ks = 0; ks < 4; ks++) {
            unsigned kb[8][2];
#pragma unroll
            for (int p = 0; p < 4; p++) {
                unsigned addr = kbuf_s +
                    ((unsigned)((p * 16 + rowp) * KH_STRIDE + ks * 8 + ksel) << 2);
                ldsm4(kb[2 * p][0], kb[2 * p][1], kb[2 * p + 1][0], kb[2 * p + 1][1], addr);
            }
#pragma unroll
            for (int nt = 0; nt < 8; nt++)
                mma_bf16(s[nt], qa[ks][0], qa[ks][1], qa[ks][2], qa[ks][3],
                         kb[nt][0], kb[nt][1]);
        }

#pragma unroll
        for (int nt = 0; nt < 8; nt++) {
            int m0 = Mb[nt * 8 + 2 * q4];
            int m1 = Mb[nt * 8 + 2 * q4 + 1];
            s[nt][0] = m0 ? s[nt][0] * scl : -4.5e18f;
            s[nt][1] = m1 ? s[nt][1] * scl : -4.5e18f;
            s[nt][2] = m0 ? s[nt][2] * scl : -4.5e18f;
            s[nt][3] = m1 ? s[nt][3] * scl : -4.5e18f;
        }

        float mx0 = s[0][0], mx1 = s[0][2];
#pragma unroll
        for (int nt = 0; nt < 8; nt++) {
            mx0 = fmaxf(mx0, fmaxf(s[nt][0], s[nt][1]));
            mx1 = fmaxf(mx1, fmaxf(s[nt][2], s[nt][3]));
        }
        mx0 = fmaxf(mx0, __shfl_xor_sync(0xffffffffu, mx0, 1));
        mx0 = fmaxf(mx0, __shfl_xor_sync(0xffffffffu, mx0, 2));
        mx1 = fmaxf(mx1, __shfl_xor_sync(0xffffffffu, mx1, 1));
        mx1 = fmaxf(mx1, __shfl_xor_sync(0xffffffffu, mx1, 2));

        float mn0 = fmaxf(mrow0, mx0);
        float mn1 = fmaxf(mrow1, mx1);
        float c0 = ex2(mrow0 - mn0);
        float c1 = ex2(mrow1 - mn1);
        mrow0 = mn0; mrow1 = mn1;

        float sum0 = 0.f, sum1 = 0.f;
#pragma unroll
        for (int nt = 0; nt < 8; nt++) {
            s[nt][0] = ex2(s[nt][0] - mn0); sum0 += s[nt][0];
            s[nt][1] = ex2(s[nt][1] - mn0); sum0 += s[nt][1];
            s[nt][2] = ex2(s[nt][2] - mn1); sum1 += s[nt][2];
            s[nt][3] = ex2(s[nt][3] - mn1); sum1 += s[nt][3];
        }
        sum0 += __shfl_xor_sync(0xffffffffu, sum0, 1);
        sum0 += __shfl_xor_sync(0xffffffffu, sum0, 2);
        sum1 += __shfl_xor_sync(0xffffffffu, sum1, 1);
        sum1 += __shfl_xor_sync(0xffffffffu, sum1, 2);
        lrow0 = lrow0 * c0 + sum0;
        lrow1 = lrow1 * c1 + sum1;

#pragma unroll
        for (int nt = 0; nt < 8; nt++) {
            o[nt][0] *= c0; o[nt][1] *= c0; o[nt][2] *= c1; o[nt][3] *= c1;
        }

        // O += P @ V (bf16 k16), V frags via ldmatrix.x4
#pragma unroll
        for (int ks = 0; ks < 4; ks++) {
            unsigned a0 = pack_bf16(s[2 * ks][0],     s[2 * ks][1]);
            unsigned a1 = pack_bf16(s[2 * ks][2],     s[2 * ks][3]);
            unsigned a2 = pack_bf16(s[2 * ks + 1][0], s[2 * ks + 1][1]);
            unsigned a3 = pack_bf16(s[2 * ks + 1][2], s[2 * ks + 1][3]);
            unsigned vb[8][2];
#pragma unroll
            for (int p = 0; p < 4; p++) {
                unsigned addr = vbuf_s +
                    ((unsigned)((p * 16 + rowp) * VT_STRIDE + ks * 8 + ksel) << 2);
                ldsm4(vb[2 * p][0], vb[2 * p][1], vb[2 * p + 1][0], vb[2 * p + 1][1], addr);
            }
#pragma unroll
            for (int nt = 0; nt < 8; nt++)
                mma_bf16(o[nt], a0, a1, a2, a3, vb[nt][0], vb[nt][1]);
        }
        __syncthreads();
    }

    const float inv0 = 1.f / lrow0;
    const float inv1 = 1.f / lrow1;
    unsigned short* Op = g_ch + (size_t)(n * LSEQ + qbase) * EMB + h * HD;
    const int row = warp * 16 + qn;
#pragma unroll
    for (int nt = 0; nt < 8; nt++) {
        int col = nt * 8 + 2 * q4;
        *(unsigned*)(Op + (size_t)row * EMB + col) =
            pack_bf16(o[nt][0] * inv0, o[nt][1] * inv0);
        *(unsigned*)(Op + (size_t)(row + 8) * EMB + col) =
            pack_bf16(o[nt][2] * inv1, o[nt][3] * inv1);
    }
}

// ---------------- Kernel 3: out = ctx @ Wo^T + bo (bf16 mma, 128x128 tile) ---
#define OG_AS_TILE (128 * 36)   // u32 per A stage
#define OG_WS_TILE (128 * 36)   // u32 per W stage
#define OG_SMEM_BYTES ((2 * OG_AS_TILE + 2 * OG_WS_TILE) * 4)

__global__ __launch_bounds__(256, 2) void ogemm_kernel(
    const float* __restrict__ bo, float* __restrict__ out)
{
    extern __shared__ unsigned usm[];
    unsigned* AS = usm;                    // [2][128][36] bf16x2
    unsigned* WS = usm + 2 * OG_AS_TILE;   // [2][128][36] bf16x2

    const int t    = threadIdx.x;
    const int warp = t >> 5;
    const int lane = t & 31;
    const int qn   = lane >> 2;
    const int q4   = lane & 3;
    const int mb   = blockIdx.y * 128;
    const int nb   = blockIdx.x * 128;

    // ldmatrix addressing
    const int rowp = ((lane >> 4) & 1) * 8 + (lane & 7);  // B-op: row in 16-pair
    const int ksel = ((lane >> 3) & 1) * 4;
    const int arow = ((lane >> 3) & 1) * 8 + (lane & 7);  // A-op: row sel
    const int akoff = (lane >> 4) * 4;

    const unsigned asm_base = (unsigned)__cvta_generic_to_shared(AS);
    const unsigned wsm_base = (unsigned)__cvta_generic_to_shared(WS);

    auto load_tile = [&](int it, int buf) {
        const int kb = it * 64;
#pragma unroll
        for (int i = 0; i < 4; i++) {
            int idx = t + i * 256;
            int row = idx >> 3;
            int c   = idx & 7;
            cpa16(&AS[buf * OG_AS_TILE + row * 36 + c * 4],
                  g_ch + (size_t)(mb + row) * 1024 + kb + c * 8);
        }
#pragma unroll
        for (int i = 0; i < 4; i++) {
            int idx = t + i * 256;
            int row = idx >> 3;
            int c   = idx & 7;
            cpa16(&WS[buf * OG_WS_TILE + row * 36 + c * 4],
                  g_woh + (size_t)(nb + row) * 1024 + kb + c * 8);
        }
        cpa_commit();
    };

    load_tile(0, 0);

    float acc[16][4];
#pragma unroll
    for (int i = 0; i < 16; i++) { acc[i][0] = acc[i][1] = acc[i][2] = acc[i][3] = 0.f; }

    const int r0b = warp * 16;
    for (int it = 0; it < 16; it++) {
        const int buf = it & 1;
        if (it < 15) {
            load_tile(it + 1, buf ^ 1);
            asm volatile("cp.async.wait_group 1;\n");
        } else {
            asm volatile("cp.async.wait_group 0;\n");
        }
        __syncthreads();

        const unsigned abuf_s = asm_base + (unsigned)(buf * OG_AS_TILE) * 4u;
        const unsigned wbuf_s = wsm_base + (unsigned)(buf * OG_WS_TILE) * 4u;
#pragma unroll
        for (int ks = 0; ks < 4; ks++) {
            unsigned a0, a1, a2, a3;
            ldsm4(a0, a1, a2, a3,
                  abuf_s + ((unsigned)((r0b + arow) * 36 + ks * 8 + akoff) << 2));
#pragma unroll
            for (int p = 0; p < 8; p++) {
                unsigned b0, b1, b2, b3;
                ldsm4(b0, b1, b2, b3,
                      wbuf_s + ((unsigned)((p * 16 + rowp) * 36 + ks * 8 + ksel) << 2));
                mma_bf16(acc[2 * p],     a0, a1, a2, a3, b0, b1);
                mma_bf16(acc[2 * p + 1], a0, a1, a2, a3, b2, b3);
            }
        }
        __syncthreads();
    }

    const int r = r0b + qn;
#pragma unroll
    for (int nt = 0; nt < 16; nt++) {
        int col = nt * 8 + 2 * q4;
        float b0 = bo[nb + col], b1 = bo[nb + col + 1];
        float2 v0; v0.x = acc[nt][0] + b0; v0.y = acc[nt][1] + b1;
        *(float2*)(out + (size_t)(mb + r) * 1024 + nb + col) = v0;
        float2 v1; v1.x = acc[nt][2] + b0; v1.y = acc[nt][3] + b1;
        *(float2*)(out + (size_t)(mb + r + 8) * 1024 + nb + col) = v1;
    }
}

extern "C" void kernel_launch(void* const* d_in, const int* in_sizes, int n_in,
                              void* d_out, int out_size) {
    const float* values = (const float*)d_in[0];
    const float* key    = (const float*)d_in[1];
    const float* query  = (const float*)d_in[2];
    const int*   mask   = (const int*)d_in[3];
    const float* Wv     = (const float*)d_in[4];
    const float* Wk     = (const float*)d_in[5];
    const float* Wq     = (const float*)d_in[6];
    const float* bq     = (const float*)d_in[7];
    const float* Wo     = (const float*)d_in[8];
    const float* bo     = (const float*)d_in[9];
    float* out = (float*)d_out;

    cudaFuncSetAttribute(flash_kernel, cudaFuncAttributeMaxDynamicSharedMemorySize,
                         FLASH_SMEM_BYTES);
    cudaFuncSetAttribute(ogemm_kernel, cudaFuncAttributeMaxDynamicSharedMemorySize,
                         OG_SMEM_BYTES);

    wconv_kernel<<<EMB * EMB / (256 * 4), 256>>>(Wo);
    proj_kernel<<<dim3(NB * LSEQ * NHD / 64, 3), 128>>>(query, key, values, Wq, Wk, Wv, bq);
    flash_kernel<<<dim3(LSEQ / 128, NB * NHD), 256, FLASH_SMEM_BYTES>>>(mask);
    ogemm_kernel<<<dim3(EMB / 128, NB * LSEQ / 128), 256, OG_SMEM_BYTES>>>(bo, out);
}